// round 13
// baseline (speedup 1.0000x reference)
#include <cuda_runtime.h>
#include <cuda_fp16.h>
#include <math.h>
#include <stdint.h>

// ---------------------------------------------------------------------------
// Model constants
// ---------------------------------------------------------------------------
#define Lc 2
#define Hc 2048
#define NHc 32
#define NKVc 4
#define HDc 64
#define Ic 5632
#define Bc 2
#define Sc 1024
#define Tc (Bc * Sc)                   // 2048 tokens
#define QKVN ((NHc + 2 * NKVc) * HDc)  // 2560
#define GUN (2 * Ic)                   // 11264
#define EPSc 1e-5f
#define WSCALE 64.0f
#define WINV   0.015625f               // 1/64
#define ROPE_LT 0.2878231366f          // ln(10000)/32

// ---------------------------------------------------------------------------
// Scratch (static device globals; no allocation allowed)
// ---------------------------------------------------------------------------
__device__ float g_res [Tc * Hc];

// fp16 activations (GEMM A operands)
__device__ __half g_hn [Tc * Hc];
__device__ __half g_at [Tc * Hc];
__device__ __half g_ac [(size_t)Tc * Ic];

// split fp16 Q (pre-scaled by 0.125) and KV caches
__device__ __half g_qh [Tc * Hc];
__device__ __half g_ql [Tc * Hc];
__device__ __half g_kh [Bc * NKVc * Sc * HDc];
__device__ __half g_kl [Bc * NKVc * Sc * HDc];
__device__ __half g_vh [Bc * NKVc * Sc * HDc];
__device__ __half g_vl [Bc * NKVc * Sc * HDc];

// RoPE cos/sin table [seq][32]
__device__ float2 g_rope[Sc * 32];

// Transposed split weights (x64 scaled, fp16 hi+lo exact 2-term):
// per layer [qkv_t(QKVN,H) | o_t(H,H) | gu_t(GUN,H, gate/up interleaved) | down_t(H,I)]
#define WT_QKV_OFF 0
#define WT_O_OFF   ((size_t)QKVN * Hc)
#define WT_GU_OFF  (WT_O_OFF + (size_t)Hc * Hc)
#define WT_DN_OFF  (WT_GU_OFF + (size_t)GUN * Hc)
#define WT_PER_L   (WT_DN_OFF + (size_t)Hc * Ic)
__device__ __half g_wh[2 * WT_PER_L];
__device__ __half g_wl[2 * WT_PER_L];

// ---------------------------------------------------------------------------
// Helpers
// ---------------------------------------------------------------------------
__device__ __forceinline__ uint32_t smem_u32(const void* p) {
    uint32_t a;
    asm("{ .reg .u64 t; cvta.to.shared.u64 t, %1; cvt.u32.u64 %0, t; }"
        : "=r"(a) : "l"(p));
    return a;
}

__device__ __forceinline__ void cp_async16(uint32_t smem_addr, const void* gptr) {
    asm volatile("cp.async.cg.shared.global [%0], [%1], 16;"
                 :: "r"(smem_addr), "l"(gptr) : "memory");
}
#define CP_COMMIT() asm volatile("cp.async.commit_group;" ::: "memory")
#define CP_WAIT0()  asm volatile("cp.async.wait_group 0;" ::: "memory")
#define CP_WAIT2()  asm volatile("cp.async.wait_group 2;" ::: "memory")

__device__ __forceinline__ void mma_f16(float* d, const uint32_t* a, const uint32_t* b) {
    asm volatile(
        "mma.sync.aligned.m16n8k16.row.col.f32.f16.f16.f32 "
        "{%0,%1,%2,%3}, {%4,%5,%6,%7}, {%8,%9}, {%0,%1,%2,%3};"
        : "+f"(d[0]), "+f"(d[1]), "+f"(d[2]), "+f"(d[3])
        : "r"(a[0]), "r"(a[1]), "r"(a[2]), "r"(a[3]),
          "r"(b[0]), "r"(b[1]));
}

#define LDSM4(R, A) \
    asm volatile("ldmatrix.sync.aligned.m8n8.x4.shared.b16 {%0,%1,%2,%3}, [%4];" \
        : "=r"((R)[0]), "=r"((R)[1]), "=r"((R)[2]), "=r"((R)[3]) : "r"(A))

#define LDSM4T(R, A) \
    asm volatile("ldmatrix.sync.aligned.m8n8.x4.trans.shared.b16 {%0,%1,%2,%3}, [%4];" \
        : "=r"((R)[0]), "=r"((R)[1]), "=r"((R)[2]), "=r"((R)[3]) : "r"(A))

__device__ __forceinline__ void split2h(float x, __half& hi, __half& lo) {
    hi = __float2half_rn(x);
    lo = __float2half_rn(x - __half2float(hi));
}

__device__ __forceinline__ uint32_t packh2(float a, float b) {
    __half2 h = __floats2half2_rn(a, b);
    return *(uint32_t*)&h;
}

// ---------------------------------------------------------------------------
// RoPE table: same expressions as the previous in-epilogue math (bit-identical)
// ---------------------------------------------------------------------------
__global__ void rope_table_kernel(const int* __restrict__ pos) {
    int s = blockIdx.x;
    int j = threadIdx.x;
    float p = (float)pos[s];
    float ang = p * __expf(-(float)j * ROPE_LT);
    g_rope[s * 32 + j] = make_float2(cosf(ang), sinf(ang));
}

// ---------------------------------------------------------------------------
// Fused weight prep: transpose + x64 scale + exact fp16 2-term split.
// gate_up destination rows interleaved (gate i -> 2i, up i -> 2i+1).
// ---------------------------------------------------------------------------
#define TILES_PER_LAYER 43008
__global__ void prep_weights(const float* __restrict__ wqkv,
                             const float* __restrict__ wo,
                             const float* __restrict__ wgu,
                             const float* __restrict__ wdn,
                             __half* __restrict__ wth,
                             __half* __restrict__ wtl) {
    __shared__ float tile[32][33];
    int bid = blockIdx.x;
    int l = 0;
    if (bid >= TILES_PER_LAYER) { l = 1; bid -= TILES_PER_LAYER; }
    size_t loff = (size_t)l * WT_PER_L;

    const float* src;
    __half *hi, *lo;
    int K, N;
    int gu_mode = 0;
    if (bid < 5120) {
        src = wqkv + (size_t)l * Hc * QKVN;
        hi = wth + loff + WT_QKV_OFF; lo = wtl + loff + WT_QKV_OFF;
        K = Hc; N = QKVN;
    } else if (bid < 9216) {
        bid -= 5120;
        src = wo + (size_t)l * Hc * Hc;
        hi = wth + loff + WT_O_OFF; lo = wtl + loff + WT_O_OFF;
        K = Hc; N = Hc;
    } else if (bid < 31744) {
        bid -= 9216;
        src = wgu + (size_t)l * Hc * GUN;
        hi = wth + loff + WT_GU_OFF; lo = wtl + loff + WT_GU_OFF;
        K = Hc; N = GUN;
        gu_mode = 1;
    } else {
        bid -= 31744;
        src = wdn + (size_t)l * Ic * Hc;
        hi = wth + loff + WT_DN_OFF; lo = wtl + loff + WT_DN_OFF;
        K = Ic; N = Hc;
    }
    int tilesX = N / 32;
    int nb = (bid % tilesX) * 32;
    int kb = (bid / tilesX) * 32;

#pragma unroll
    for (int i = threadIdx.y; i < 32; i += 8)
        tile[i][threadIdx.x] = src[(size_t)(kb + i) * N + nb + threadIdx.x];
    __syncthreads();
#pragma unroll
    for (int i = threadIdx.y; i < 32; i += 8) {
        float v = tile[threadIdx.x][i] * WSCALE;
        __half h, lv;
        split2h(v, h, lv);
        int col = nb + i;
        if (gu_mode) col = (col < Ic) ? (2 * col) : (2 * (col - Ic) + 1);
        size_t idx = (size_t)col * K + kb + threadIdx.x;
        hi[idx] = h;
        lo[idx] = lv;
    }
}

// ---------------------------------------------------------------------------
// fp16 GEMM, templated on weight TERMS (2 = exact split, 1 = fp16 weights).
// Epilogue modes:
//   actout != nullptr : interleaved (gate,up) cols -> silu(g)*u fp16
//   qh     != nullptr : QKV mode -> RoPE (table) + split-fp16 scatter
//   else              : fp32 C (+ optional addend)
// ---------------------------------------------------------------------------
#define RPITCH 48
#define ARRB   (128 * RPITCH)
#define STAGEB (3 * ARRB)
#define GEMM_SMEM (4 * STAGEB)

template <int TERMS>
__global__ void __launch_bounds__(256, 2)
gemm_f16(const __half* __restrict__ A,
         const __half* __restrict__ Wh,
         const __half* __restrict__ Wl,
         float* __restrict__ C, const float* __restrict__ addend,
         __half* __restrict__ actout,
         __half* __restrict__ qh, __half* __restrict__ ql,
         __half* __restrict__ kh, __half* __restrict__ kl,
         __half* __restrict__ vh, __half* __restrict__ vl,
         int M, int N, int K) {
    extern __shared__ char smraw[];
    uint32_t sbase = smem_u32(smraw);

    const int tid  = threadIdx.x;
    const int warp = tid >> 5;
    const int lane = tid & 31;
    const int wm   = (warp >> 1) * 32;
    const int wn   = (warp & 1) * 64;
    const int grp  = lane >> 2;
    const int tig  = lane & 3;

    const int m0 = blockIdx.x * 128;
    const int n0 = blockIdx.y * 128;

    const int li = lane >> 3;
    const int lr = lane & 7;
    const uint32_t aoffl = (uint32_t)(((li & 1) * 8 + lr) * RPITCH + (li >> 1) * 16);
    const uint32_t boffl = (uint32_t)(((li >> 1) * 8 + lr) * RPITCH + (li & 1) * 16);

    const int r0   = tid >> 1;
    const int half = tid & 1;
    const uint32_t sdst = (uint32_t)(r0 * RPITCH + half * 16);
    const __half* pA  = A  + (size_t)(m0 + r0) * K + half * 8;
    const __half* pWh = Wh + (size_t)(n0 + r0) * K + half * 8;
    const __half* pWl = (TERMS == 2) ? (Wl + (size_t)(n0 + r0) * K + half * 8) : nullptr;

    const int nkt = K >> 4;

    float c[2][8][4];
#pragma unroll
    for (int mt = 0; mt < 2; mt++)
#pragma unroll
        for (int nt = 0; nt < 8; nt++)
#pragma unroll
            for (int i = 0; i < 4; i++) c[mt][nt][i] = 0.f;

#pragma unroll
    for (int s = 0; s < 3; s++) {
        uint32_t b = sbase + (uint32_t)s * STAGEB + sdst;
        int ko = s * 16;
        cp_async16(b,            pA  + ko);
        cp_async16(b + ARRB,     pWh + ko);
        if (TERMS == 2) cp_async16(b + 2 * ARRB, pWl + ko);
        CP_COMMIT();
    }

    for (int kt = 0; kt < nkt; kt++) {
        CP_WAIT2();
        __syncthreads();

        uint32_t sb = sbase + (uint32_t)(kt & 3) * STAGEB;

        uint32_t a[2][4];
#pragma unroll
        for (int mt = 0; mt < 2; mt++) {
            uint32_t aaddr = sb + (uint32_t)((wm + mt * 16) * RPITCH) + aoffl;
            LDSM4(a[mt], aaddr);
        }
#pragma unroll
        for (int nh = 0; nh < 2; nh++) {
            uint32_t wh[2][4], wl[2][4];
#pragma unroll
            for (int pq = 0; pq < 2; pq++) {
                uint32_t baddr = sb + ARRB +
                                 (uint32_t)((wn + nh * 32 + pq * 16) * RPITCH) + boffl;
                LDSM4(wh[pq], baddr);
                if (TERMS == 2) LDSM4(wl[pq], baddr + ARRB);
            }
#pragma unroll
            for (int mt = 0; mt < 2; mt++)
#pragma unroll
                for (int pq = 0; pq < 2; pq++)
#pragma unroll
                    for (int h = 0; h < 2; h++)
                        mma_f16(c[mt][nh * 4 + pq * 2 + h], a[mt], &wh[pq][h * 2]);
            if (TERMS == 2) {
#pragma unroll
                for (int mt = 0; mt < 2; mt++)
#pragma unroll
                    for (int pq = 0; pq < 2; pq++)
#pragma unroll
                        for (int h = 0; h < 2; h++)
                            mma_f16(c[mt][nh * 4 + pq * 2 + h], a[mt], &wl[pq][h * 2]);
            }
        }

        if (kt + 3 < nkt) {
            uint32_t b = sbase + (uint32_t)((kt + 3) & 3) * STAGEB + sdst;
            int ko = (kt + 3) * 16;
            cp_async16(b,            pA  + ko);
            cp_async16(b + ARRB,     pWh + ko);
            if (TERMS == 2) cp_async16(b + 2 * ARRB, pWl + ko);
        }
        CP_COMMIT();
    }

    if (actout) {
#pragma unroll
        for (int mt = 0; mt < 2; mt++) {
            int row = m0 + wm + mt * 16 + grp;
#pragma unroll
            for (int nt = 0; nt < 8; nt++) {
                int col = n0 + wn + nt * 8 + tig * 2;
                int pair = col >> 1;
                {
                    float g = c[mt][nt][0] * WINV;
                    float u = c[mt][nt][1] * WINV;
                    float sig = 1.0f / (1.0f + __expf(-g));
                    actout[(size_t)row * Ic + pair] = __float2half_rn(g * sig * u);
                }
                {
                    float g = c[mt][nt][2] * WINV;
                    float u = c[mt][nt][3] * WINV;
                    float sig = 1.0f / (1.0f + __expf(-g));
                    actout[(size_t)(row + 8) * Ic + pair] = __float2half_rn(g * sig * u);
                }
            }
        }
    } else if (qh) {
        // QKV mode: RoPE via table + split-fp16 scatter.
        int head64 = n0 + wn;
#pragma unroll
        for (int mt = 0; mt < 2; mt++) {
#pragma unroll
            for (int r = 0; r < 2; r++) {
                int tok = m0 + wm + mt * 16 + grp + r * 8;
                int bb = tok / Sc;
                int ss = tok - bb * Sc;
                const float2* rt = g_rope + ss * 32;
                if (head64 < NHc * HDc) {
                    int head = head64 >> 6;
                    size_t base = (size_t)tok * Hc + head * HDc;
#pragma unroll
                    for (int nt = 0; nt < 4; nt++) {
#pragma unroll
                        for (int e = 0; e < 2; e++) {
                            int j = nt * 8 + tig * 2 + e;
                            float x1 = c[mt][nt][r * 2 + e] * WINV;
                            float x2 = c[mt][nt + 4][r * 2 + e] * WINV;
                            float2 cs = rt[j];
                            float r1 = (x1 * cs.x - x2 * cs.y) * 0.125f;
                            float r2 = (x2 * cs.x + x1 * cs.y) * 0.125f;
                            __half h1, l1, h2, l2;
                            split2h(r1, h1, l1);
                            split2h(r2, h2, l2);
                            qh[base + j] = h1;       ql[base + j] = l1;
                            qh[base + j + 32] = h2;  ql[base + j + 32] = l2;
                        }
                    }
                } else if (head64 < (NHc + NKVc) * HDc) {
                    int hk = (head64 - NHc * HDc) >> 6;
                    size_t base = (((size_t)(bb * NKVc + hk)) * Sc + ss) * HDc;
#pragma unroll
                    for (int nt = 0; nt < 4; nt++) {
#pragma unroll
                        for (int e = 0; e < 2; e++) {
                            int j = nt * 8 + tig * 2 + e;
                            float x1 = c[mt][nt][r * 2 + e] * WINV;
                            float x2 = c[mt][nt + 4][r * 2 + e] * WINV;
                            float2 cs = rt[j];
                            float r1 = x1 * cs.x - x2 * cs.y;
                            float r2 = x2 * cs.x + x1 * cs.y;
                            __half h1, l1, h2, l2;
                            split2h(r1, h1, l1);
                            split2h(r2, h2, l2);
                            kh[base + j] = h1;       kl[base + j] = l1;
                            kh[base + j + 32] = h2;  kl[base + j + 32] = l2;
                        }
                    }
                } else {
                    int hv = (head64 - (NHc + NKVc) * HDc) >> 6;
                    size_t base = (((size_t)(bb * NKVc + hv)) * Sc + ss) * HDc;
#pragma unroll
                    for (int nt = 0; nt < 8; nt++) {
#pragma unroll
                        for (int e = 0; e < 2; e++) {
                            int d = nt * 8 + tig * 2 + e;
                            float v = c[mt][nt][r * 2 + e] * WINV;
                            __half h1, l1;
                            split2h(v, h1, l1);
                            vh[base + d] = h1;  vl[base + d] = l1;
                        }
                    }
                }
            }
        }
    } else {
#pragma unroll
        for (int mt = 0; mt < 2; mt++) {
            int row = m0 + wm + mt * 16 + grp;
#pragma unroll
            for (int nt = 0; nt < 8; nt++) {
                int col = n0 + wn + nt * 8 + tig * 2;
                size_t i0 = (size_t)row * N + col;
                size_t i1 = (size_t)(row + 8) * N + col;
                float2 v0 = make_float2(c[mt][nt][0] * WINV, c[mt][nt][1] * WINV);
                float2 v1 = make_float2(c[mt][nt][2] * WINV, c[mt][nt][3] * WINV);
                if (addend) {
                    float2 a0 = *(const float2*)(addend + i0);
                    float2 a1 = *(const float2*)(addend + i1);
                    v0.x += a0.x; v0.y += a0.y;
                    v1.x += a1.x; v1.y += a1.y;
                }
                *(float2*)(C + i0) = v0;
                *(float2*)(C + i1) = v1;
            }
        }
    }
}

// ---------------------------------------------------------------------------
// Embedding gather
// ---------------------------------------------------------------------------
__global__ void embed_kernel(const int* __restrict__ ids,
                             const float* __restrict__ embed,
                             float* __restrict__ res) {
    int t = blockIdx.x;
    int id = ids[t];
    const float4* src = (const float4*)(embed + (size_t)id * Hc);
    float4* dst = (float4*)(res + (size_t)t * Hc);
    for (int i = threadIdx.x; i < Hc / 4; i += blockDim.x)
        dst[i] = src[i];
}

// ---------------------------------------------------------------------------
// RMSNorm. Output fp32 and/or fp16.
// ---------------------------------------------------------------------------
__global__ void addnorm_kernel(const float* __restrict__ res,
                               const float* __restrict__ w,
                               float* __restrict__ outf,
                               __half* __restrict__ oh) {
    int t = blockIdx.x;
    int tid = threadIdx.x;
    const float* rp = res + (size_t)t * Hc;
    float vals[8];
    float ss = 0.f;
#pragma unroll
    for (int i = 0; i < 8; i++) {
        int idx = tid + i * 256;
        float v = rp[idx];
        vals[i] = v;
        ss += v * v;
    }
    __shared__ float warp_s[8];
#pragma unroll
    for (int off = 16; off > 0; off >>= 1)
        ss += __shfl_down_sync(0xffffffff, ss, off);
    if ((tid & 31) == 0) warp_s[tid >> 5] = ss;
    __syncthreads();
    if (tid < 8) {
        float v = warp_s[tid];
#pragma unroll
        for (int off = 4; off > 0; off >>= 1)
            v += __shfl_down_sync(0xff, v, off);
        if (tid == 0) warp_s[0] = v;
    }
    __syncthreads();
    float inv = rsqrtf(warp_s[0] * (1.0f / Hc) + EPSc);
#pragma unroll
    for (int i = 0; i < 8; i++) {
        int idx = tid + i * 256;
        float o = vals[i] * inv * w[idx];
        if (outf) outf[(size_t)t * Hc + idx] = o;
        if (oh)   oh[(size_t)t * Hc + idx] = __float2half_rn(o);
    }
}

// ---------------------------------------------------------------------------
// Flash attention on fp16 MMA. One block = 128 queries of one (b, head),
// 8 warps x 16 rows, 256 threads. K/V tiles of 64 keys, double-buffered.
// QK: 3-term split (exact). PV: P 2-term x V 2-term (3 terms).
// Heavy blocks (large qb) scheduled first.
// ---------------------------------------------------------------------------
#define FPITCHB 144
#define FARR    (64 * FPITCHB)
#define FBUF    (4 * FARR)
#define FLASH_SMEM (2 * FBUF)

__global__ void __launch_bounds__(256)
flash_mma(const __half* __restrict__ qhg, const __half* __restrict__ qlg,
          const __half* __restrict__ khg, const __half* __restrict__ klg,
          const __half* __restrict__ vhg, const __half* __restrict__ vlg,
          __half* __restrict__ aout) {
    extern __shared__ char smraw[];
    uint32_t sbase = smem_u32(smraw);

    const int qb = (int)gridDim.x - 1 - (int)blockIdx.x;   // heavy-first
    const int h  = blockIdx.y;
    const int b  = blockIdx.z;
    const int hkv = h / (NHc / NKVc);
    const int tid = threadIdx.x;
    const int w   = tid >> 5;            // 0..7
    const int lane = tid & 31;
    const int grp = lane >> 2;
    const int tig = lane & 3;
    const int li = lane >> 3;
    const int lr = lane & 7;
    const uint32_t boffl = (uint32_t)(((li >> 1) * 8 + lr) * FPITCHB + (li & 1) * 16);
    const uint32_t voffl = (uint32_t)(((li & 1) * 8 + lr) * FPITCHB + (li >> 1) * 16);

    // Q fragments in registers (queries qb*128 + w*16 + grp (+8))
    uint32_t qfh[4][4], qfl[4][4];
    {
        int row0 = b * Sc + qb * 128 + w * 16 + grp;
#pragma unroll
        for (int kt = 0; kt < 4; kt++) {
#pragma unroll
            for (int i = 0; i < 4; i++) {
                int row = row0 + (i & 1) * 8;
                int col = h * HDc + kt * 16 + (i >> 1) * 8 + tig * 2;
                qfh[kt][i] = *(const uint32_t*)&qhg[(size_t)row * Hc + col];
                qfl[kt][i] = *(const uint32_t*)&qlg[(size_t)row * Hc + col];
            }
        }
    }

    float o[8][4];
#pragma unroll
    for (int dn = 0; dn < 8; dn++)
#pragma unroll
        for (int i = 0; i < 4; i++) o[dn][i] = 0.f;
    float m0 = -1e30f, m1 = -1e30f, l0 = 0.f, l1 = 0.f;

    const size_t kvbase = ((size_t)(b * NKVc + hkv)) * Sc;
    const int nkb = 2 * qb + 2;          // 64-key tiles covering causal span

    // prologue: kb=0 -> buffer 0 (256 threads: 2 chunks per array each)
    {
        uint32_t bb = sbase;
#pragma unroll
        for (int i = 0; i < 2; i++) {
            int chunk = tid + i * 256;
            int r = chunk >> 3, cc = chunk & 7;
            uint32_t so = (uint32_t)(r * FPITCHB + cc * 16);
            size_t go = (kvbase + r) * HDc + cc * 8;
            cp_async16(bb + so,            khg + go);
            cp_async16(bb + FARR + so,     klg + go);
            cp_async16(bb + 2 * FARR + so, vhg + go);
            cp_async16(bb + 3 * FARR + so, vlg + go);
        }
        CP_COMMIT();
    }

    for (int kb = 0; kb < nkb; kb++) {
        CP_WAIT0();
        __syncthreads();

        if (kb + 1 < nkb) {
            uint32_t bb = sbase + (uint32_t)((kb + 1) & 1) * FBUF;
#pragma unroll
            for (int i = 0; i < 2; i++) {
                int chunk = tid + i * 256;
                int r = chunk >> 3, cc = chunk & 7;
                uint32_t so = (uint32_t)(r * FPITCHB + cc * 16);
                size_t go = (kvbase + (kb + 1) * 64 + r) * HDc + cc * 8;
                cp_async16(bb + so,            khg + go);
                cp_async16(bb + FARR + so,     klg + go);
                cp_async16(bb + 2 * FARR + so, vhg + go);
                cp_async16(bb + 3 * FARR + so, vlg + go);
            }
            CP_COMMIT();
        }

        uint32_t sb = sbase + (uint32_t)(kb & 1) * FBUF;

        float s[8][4];
#pragma unroll
        for (int nt = 0; nt < 8; nt++)
#pragma unroll
            for (int i = 0; i < 4; i++) s[nt][i] = 0.f;

#pragma unroll
        for (int kt = 0; kt < 4; kt++) {
            uint32_t kfh[4][4], kfl[4][4];
#pragma unroll
            for (int kg = 0; kg < 4; kg++) {
                uint32_t addr = sb + (uint32_t)(kg * 16 * FPITCHB) + (uint32_t)(kt * 32) + boffl;
                LDSM4(kfh[kg], addr);
                LDSM4(kfl[kg], addr + FARR);
            }
#pragma unroll
            for (int kg = 0; kg < 4; kg++)
#pragma unroll
                for (int hh = 0; hh < 2; hh++)
                    mma_f16(s[kg * 2 + hh], qfh[kt], &kfh[kg][hh * 2]);
#pragma unroll
            for (int kg = 0; kg < 4; kg++)
#pragma unroll
                for (int hh = 0; hh < 2; hh++)
                    mma_f16(s[kg * 2 + hh], qfh[kt], &kfl[kg][hh * 2]);
#pragma unroll
            for (int kg = 0; kg < 4; kg++)
#pragma unroll
                for (int hh = 0; hh < 2; hh++)
                    mma_f16(s[kg * 2 + hh], qfl[kt], &kfh[kg][hh * 2]);
        }

        // causal mask for tiles intersecting/above the diagonal
        if (kb >= 2 * qb) {
            int grow0 = qb * 128 + w * 16 + grp;   // global query position
            int grow1 = grow0 + 8;
#pragma unroll
            for (int nt = 0; nt < 8; nt++) {
                int gcol = kb * 64 + nt * 8 + tig * 2;
                if (gcol     > grow0) s[nt][0] = -1e30f;
                if (gcol + 1 > grow0) s[nt][1] = -1e30f;
                if (gcol     > grow1) s[nt][2] = -1e30f;
                if (gcol + 1 > grow1) s[nt][3] = -1e30f;
            }
        }

        {
            float mx0 = -1e30f, mx1 = -1e30f;
#pragma unroll
            for (int nt = 0; nt < 8; nt++) {
                mx0 = fmaxf(mx0, fmaxf(s[nt][0], s[nt][1]));
                mx1 = fmaxf(mx1, fmaxf(s[nt][2], s[nt][3]));
            }
            mx0 = fmaxf(mx0, __shfl_xor_sync(0xffffffffu, mx0, 1));
            mx0 = fmaxf(mx0, __shfl_xor_sync(0xffffffffu, mx0, 2));
            mx1 = fmaxf(mx1, __shfl_xor_sync(0xffffffffu, mx1, 1));
            mx1 = fmaxf(mx1, __shfl_xor_sync(0xffffffffu, mx1, 2));
            float mn0 = fmaxf(m0, mx0);
            float mn1 = fmaxf(m1, mx1);
            float a0 = __expf(m0 - mn0);
            float a1 = __expf(m1 - mn1);
            float su0 = 0.f, su1 = 0.f;
#pragma unroll
            for (int nt = 0; nt < 8; nt++) {
                s[nt][0] = __expf(s[nt][0] - mn0); su0 += s[nt][0];
                s[nt][1] = __expf(s[nt][1] - mn0); su0 += s[nt][1];
                s[nt][2] = __expf(s[nt][2] - mn1); su1 += s[nt][2];
                s[nt][3] = __expf(s[nt][3] - mn1); su1 += s[nt][3];
            }
            su0 += __shfl_xor_sync(0xffffffffu, su0, 1);
            su0 += __shfl_xor_sync(0xffffffffu, su0, 2);
            su1 += __shfl_xor_sync(0xffffffffu, su1, 1);
            su1 += __shfl_xor_sync(0xffffffffu, su1, 2);
            l0 = l0 * a0 + su0;
            l1 = l1 * a1 + su1;
            m0 = mn0;
            m1 = mn1;
#pragma unroll
            for (int dn = 0; dn < 8; dn++) {
                o[dn][0] *= a0; o[dn][1] *= a0;
                o[dn][2] *= a1; o[dn][3] *= a1;
            }
        }

        // PV with exact 2-term P: Phi*Vhi + Phi*Vlo + Plo*Vhi
#pragma unroll
        for (int kt = 0; kt < 4; kt++) {
            uint32_t ah[4], al[4];
#pragma unroll
            for (int q4 = 0; q4 < 4; q4++) {
                int nt = 2 * kt + (q4 >> 1);
                int bs = (q4 & 1) * 2;
                float p0 = s[nt][bs], p1 = s[nt][bs + 1];
                __half h0 = __float2half_rn(p0);
                __half h1v = __float2half_rn(p1);
                float lo0 = p0 - __half2float(h0);
                float lo1 = p1 - __half2float(h1v);
                __half2 hp; hp.x = h0; hp.y = h1v;
                ah[q4] = *(uint32_t*)&hp;
                al[q4] = packh2(lo0, lo1);
            }
            uint32_t vfh[4][4], vfl[4][4];
#pragma unroll
            for (int db = 0; db < 4; db++) {
                uint32_t addr = sb + 2 * FARR + (uint32_t)(kt * 16 * FPITCHB) + (uint32_t)(db * 32) + voffl;
                LDSM4T(vfh[db], addr);
                LDSM4T(vfl[db], addr + FARR);
            }
#pragma unroll
            for (int db = 0; db < 4; db++)
#pragma unroll
                for (int hh = 0; hh < 2; hh++)
                    mma_f16(o[db * 2 + hh], ah, &vfh[db][hh * 2]);
#pragma unroll
            for (int db = 0; db < 4; db++)
#pragma unroll
                for (int hh = 0; hh < 2; hh++)
                    mma_f16(o[db * 2 + hh], ah, &vfl[db][hh * 2]);
#pragma unroll
            for (int db = 0; db < 4; db++)
#pragma unroll
                for (int hh = 0; hh < 2; hh++)
                    mma_f16(o[db * 2 + hh], al, &vfh[db][hh * 2]);
        }
    }

    {
        float i0 = 1.0f / l0;
        float i1 = 1.0f / l1;
        size_t row0 = (size_t)(b * Sc + qb * 128 + w * 16 + grp);
#pragma unroll
        for (int dn = 0; dn < 8; dn++) {
            int col = h * HDc + dn * 8 + tig * 2;
            __half2 p0 = __floats2half2_rn(o[dn][0] * i0, o[dn][1] * i0);
            __half2 p1 = __floats2half2_rn(o[dn][2] * i1, o[dn][3] * i1);
            *(__half2*)&aout[row0 * Hc + col] = p0;
            *(__half2*)&aout[(row0 + 8) * Hc + col] = p1;
        }
    }
}

// ---------------------------------------------------------------------------
// Launch
// ---------------------------------------------------------------------------
extern "C" void kernel_launch(void* const* d_in, const int* in_sizes, int n_in,
                              void* d_out, int out_size) {
    const int*   input_ids = (const int*)d_in[0];
    const int*   positions = (const int*)d_in[1];
    const float* embed     = (const float*)d_in[2];
    const float* w_qkv     = (const float*)d_in[3];
    const float* w_o       = (const float*)d_in[4];
    const float* w_gate_up = (const float*)d_in[5];
    const float* w_down    = (const float*)d_in[6];
    const float* ln1_w     = (const float*)d_in[7];
    const float* ln2_w     = (const float*)d_in[8];
    const float* norm_w    = (const float*)d_in[9];
    float* out = (float*)d_out;

    float *res;
    __half *hn, *at, *ac, *wh, *wl, *qh, *ql, *kh, *kl, *vh, *vl;
    cudaGetSymbolAddress((void**)&res,  g_res);
    cudaGetSymbolAddress((void**)&hn,   g_hn);
    cudaGetSymbolAddress((void**)&at,   g_at);
    cudaGetSymbolAddress((void**)&ac,   g_ac);
    cudaGetSymbolAddress((void**)&wh,   g_wh);
    cudaGetSymbolAddress((void**)&wl,   g_wl);
    cudaGetSymbolAddress((void**)&qh,   g_qh);
    cudaGetSymbolAddress((void**)&ql,   g_ql);
    cudaGetSymbolAddress((void**)&kh,   g_kh);
    cudaGetSymbolAddress((void**)&kl,   g_kl);
    cudaGetSymbolAddress((void**)&vh,   g_vh);
    cudaGetSymbolAddress((void**)&vl,   g_vl);

    cudaFuncSetAttribute(flash_mma, cudaFuncAttributeMaxDynamicSharedMemorySize, FLASH_SMEM);
    cudaFuncSetAttribute(gemm_f16<2>, cudaFuncAttributeMaxDynamicSharedMemorySize, GEMM_SMEM);
    cudaFuncSetAttribute(gemm_f16<1>, cudaFuncAttributeMaxDynamicSharedMemorySize, GEMM_SMEM);

    prep_weights<<<2 * TILES_PER_LAYER, dim3(32, 8)>>>(
        w_qkv, w_o, w_gate_up, w_down, wh, wl);
    rope_table_kernel<<<Sc, 32>>>(positions);

    embed_kernel<<<Tc, 256>>>(input_ids, embed, res);

    for (int l = 0; l < Lc; l++) {
        __half* whl = wh + (size_t)l * WT_PER_L;
        __half* wll = wl + (size_t)l * WT_PER_L;

        addnorm_kernel<<<Tc, 256>>>(res, ln1_w + (size_t)l * Hc, nullptr, hn);

        // QKV projection with fused RoPE (table) + split-fp16 scatter
        gemm_f16<2><<<dim3(Tc / 128, QKVN / 128), 256, GEMM_SMEM>>>(
            hn, whl + WT_QKV_OFF, wll + WT_QKV_OFF, nullptr, nullptr, nullptr,
            qh, ql, kh, kl, vh, vl, Tc, QKVN, Hc);

        flash_mma<<<dim3(Sc / 128, NHc, Bc), 256, FLASH_SMEM>>>(
            qh, ql, kh, kl, vh, vl, at);

        gemm_f16<2><<<dim3(Tc / 128, Hc / 128), 256, GEMM_SMEM>>>(
            at, whl + WT_O_OFF, wll + WT_O_OFF, res, res, nullptr,
            nullptr, nullptr, nullptr, nullptr, nullptr, nullptr,
            Tc, Hc, Hc);

        addnorm_kernel<<<Tc, 256>>>(res, ln2_w + (size_t)l * Hc, nullptr, hn);

        gemm_f16<1><<<dim3(Tc / 128, GUN / 128), 256, GEMM_SMEM>>>(
            hn, whl + WT_GU_OFF, nullptr, nullptr, nullptr, ac,
            nullptr, nullptr, nullptr, nullptr, nullptr, nullptr,
            Tc, GUN, Hc);

        gemm_f16<1><<<dim3(Tc / 128, Hc / 128), 256, GEMM_SMEM>>>(
            ac, whl + WT_DN_OFF, nullptr, res, res, nullptr,
            nullptr, nullptr, nullptr, nullptr, nullptr, nullptr,
            Tc, Hc, Ic);
    }

    addnorm_kernel<<<Tc, 256>>>(res, norm_w, out, nullptr);
}

// round 14
// speedup vs baseline: 1.0117x; 1.0117x over previous
#include <cuda_runtime.h>
#include <cuda_fp16.h>
#include <math.h>
#include <stdint.h>

// ---------------------------------------------------------------------------
// Model constants
// ---------------------------------------------------------------------------
#define Lc 2
#define Hc 2048
#define NHc 32
#define NKVc 4
#define HDc 64
#define Ic 5632
#define Bc 2
#define Sc 1024
#define Tc (Bc * Sc)                   // 2048 tokens
#define QKVN ((NHc + 2 * NKVc) * HDc)  // 2560
#define GUN (2 * Ic)                   // 11264
#define EPSc 1e-5f
#define WSCALE 64.0f
#define WINV   0.015625f               // 1/64
#define ROPE_LT 0.2878231366f          // ln(10000)/32

// ---------------------------------------------------------------------------
// Scratch (static device globals; no allocation allowed)
// ---------------------------------------------------------------------------
__device__ float g_res [Tc * Hc];

// fp16 activations (GEMM A operands)
__device__ __half g_hn [Tc * Hc];
__device__ __half g_at [Tc * Hc];
__device__ __half g_ac [(size_t)Tc * Ic];

// split fp16 Q (pre-scaled by 0.125) and KV caches
__device__ __half g_qh [Tc * Hc];
__device__ __half g_ql [Tc * Hc];
__device__ __half g_kh [Bc * NKVc * Sc * HDc];
__device__ __half g_kl [Bc * NKVc * Sc * HDc];
__device__ __half g_vh [Bc * NKVc * Sc * HDc];
__device__ __half g_vl [Bc * NKVc * Sc * HDc];

// RoPE cos/sin table [seq][32]
__device__ float2 g_rope[Sc * 32];

// Transposed split weights (x64 scaled, fp16 hi+lo exact 2-term):
// per layer [qkv_t(QKVN,H) | o_t(H,H) | gu_t(GUN,H, gate/up interleaved) | down_t(H,I)]
#define WT_QKV_OFF 0
#define WT_O_OFF   ((size_t)QKVN * Hc)
#define WT_GU_OFF  (WT_O_OFF + (size_t)Hc * Hc)
#define WT_DN_OFF  (WT_GU_OFF + (size_t)GUN * Hc)
#define WT_PER_L   (WT_DN_OFF + (size_t)Hc * Ic)
__device__ __half g_wh[2 * WT_PER_L];
__device__ __half g_wl[2 * WT_PER_L];

// ---------------------------------------------------------------------------
// Helpers
// ---------------------------------------------------------------------------
__device__ __forceinline__ uint32_t smem_u32(const void* p) {
    uint32_t a;
    asm("{ .reg .u64 t; cvta.to.shared.u64 t, %1; cvt.u32.u64 %0, t; }"
        : "=r"(a) : "l"(p));
    return a;
}

__device__ __forceinline__ void cp_async16(uint32_t smem_addr, const void* gptr) {
    asm volatile("cp.async.cg.shared.global [%0], [%1], 16;"
                 :: "r"(smem_addr), "l"(gptr) : "memory");
}
#define CP_COMMIT() asm volatile("cp.async.commit_group;" ::: "memory")
#define CP_WAIT0()  asm volatile("cp.async.wait_group 0;" ::: "memory")
#define CP_WAIT2()  asm volatile("cp.async.wait_group 2;" ::: "memory")

__device__ __forceinline__ void mma_f16(float* d, const uint32_t* a, const uint32_t* b) {
    asm volatile(
        "mma.sync.aligned.m16n8k16.row.col.f32.f16.f16.f32 "
        "{%0,%1,%2,%3}, {%4,%5,%6,%7}, {%8,%9}, {%0,%1,%2,%3};"
        : "+f"(d[0]), "+f"(d[1]), "+f"(d[2]), "+f"(d[3])
        : "r"(a[0]), "r"(a[1]), "r"(a[2]), "r"(a[3]),
          "r"(b[0]), "r"(b[1]));
}

#define LDSM4(R, A) \
    asm volatile("ldmatrix.sync.aligned.m8n8.x4.shared.b16 {%0,%1,%2,%3}, [%4];" \
        : "=r"((R)[0]), "=r"((R)[1]), "=r"((R)[2]), "=r"((R)[3]) : "r"(A))

#define LDSM4T(R, A) \
    asm volatile("ldmatrix.sync.aligned.m8n8.x4.trans.shared.b16 {%0,%1,%2,%3}, [%4];" \
        : "=r"((R)[0]), "=r"((R)[1]), "=r"((R)[2]), "=r"((R)[3]) : "r"(A))

__device__ __forceinline__ void split2h(float x, __half& hi, __half& lo) {
    hi = __float2half_rn(x);
    lo = __float2half_rn(x - __half2float(hi));
}

__device__ __forceinline__ uint32_t packh2(float a, float b) {
    __half2 h = __floats2half2_rn(a, b);
    return *(uint32_t*)&h;
}

// ---------------------------------------------------------------------------
// RoPE table (bit-identical expressions to the fused-epilogue math)
// ---------------------------------------------------------------------------
__global__ void rope_table_kernel(const int* __restrict__ pos) {
    int s = blockIdx.x;
    int j = threadIdx.x;
    float p = (float)pos[s];
    float ang = p * __expf(-(float)j * ROPE_LT);
    g_rope[s * 32 + j] = make_float2(cosf(ang), sinf(ang));
}

// ---------------------------------------------------------------------------
// Fused weight prep: transpose + x64 scale + exact fp16 2-term split.
// gate_up destination rows interleaved (gate i -> 2i, up i -> 2i+1).
// ---------------------------------------------------------------------------
#define TILES_PER_LAYER 43008
__global__ void prep_weights(const float* __restrict__ wqkv,
                             const float* __restrict__ wo,
                             const float* __restrict__ wgu,
                             const float* __restrict__ wdn,
                             __half* __restrict__ wth,
                             __half* __restrict__ wtl) {
    __shared__ float tile[32][33];
    int bid = blockIdx.x;
    int l = 0;
    if (bid >= TILES_PER_LAYER) { l = 1; bid -= TILES_PER_LAYER; }
    size_t loff = (size_t)l * WT_PER_L;

    const float* src;
    __half *hi, *lo;
    int K, N;
    int gu_mode = 0;
    if (bid < 5120) {
        src = wqkv + (size_t)l * Hc * QKVN;
        hi = wth + loff + WT_QKV_OFF; lo = wtl + loff + WT_QKV_OFF;
        K = Hc; N = QKVN;
    } else if (bid < 9216) {
        bid -= 5120;
        src = wo + (size_t)l * Hc * Hc;
        hi = wth + loff + WT_O_OFF; lo = wtl + loff + WT_O_OFF;
        K = Hc; N = Hc;
    } else if (bid < 31744) {
        bid -= 9216;
        src = wgu + (size_t)l * Hc * GUN;
        hi = wth + loff + WT_GU_OFF; lo = wtl + loff + WT_GU_OFF;
        K = Hc; N = GUN;
        gu_mode = 1;
    } else {
        bid -= 31744;
        src = wdn + (size_t)l * Ic * Hc;
        hi = wth + loff + WT_DN_OFF; lo = wtl + loff + WT_DN_OFF;
        K = Ic; N = Hc;
    }
    int tilesX = N / 32;
    int nb = (bid % tilesX) * 32;
    int kb = (bid / tilesX) * 32;

#pragma unroll
    for (int i = threadIdx.y; i < 32; i += 8)
        tile[i][threadIdx.x] = src[(size_t)(kb + i) * N + nb + threadIdx.x];
    __syncthreads();
#pragma unroll
    for (int i = threadIdx.y; i < 32; i += 8) {
        float v = tile[threadIdx.x][i] * WSCALE;
        __half h, lv;
        split2h(v, h, lv);
        int col = nb + i;
        if (gu_mode) col = (col < Ic) ? (2 * col) : (2 * (col - Ic) + 1);
        size_t idx = (size_t)col * K + kb + threadIdx.x;
        hi[idx] = h;
        lo[idx] = lv;
    }
}

// ---------------------------------------------------------------------------
// fp16 GEMM, templated on weight TERMS (2 = exact split, 1 = fp16 weights).
// Epilogue modes:
//   actout != nullptr : interleaved (gate,up) cols -> silu(g)*u fp16
//   qh     != nullptr : QKV mode -> RoPE (table) + split-fp16 scatter
//   else              : fp32 C (+ optional addend)
// ---------------------------------------------------------------------------
#define RPITCH 48
#define ARRB   (128 * RPITCH)
#define STAGEB (3 * ARRB)
#define GEMM_SMEM (4 * STAGEB)

template <int TERMS>
__global__ void __launch_bounds__(256, 2)
gemm_f16(const __half* __restrict__ A,
         const __half* __restrict__ Wh,
         const __half* __restrict__ Wl,
         float* __restrict__ C, const float* __restrict__ addend,
         __half* __restrict__ actout,
         __half* __restrict__ qh, __half* __restrict__ ql,
         __half* __restrict__ kh, __half* __restrict__ kl,
         __half* __restrict__ vh, __half* __restrict__ vl,
         int M, int N, int K) {
    extern __shared__ char smraw[];
    uint32_t sbase = smem_u32(smraw);

    const int tid  = threadIdx.x;
    const int warp = tid >> 5;
    const int lane = tid & 31;
    const int wm   = (warp >> 1) * 32;
    const int wn   = (warp & 1) * 64;
    const int grp  = lane >> 2;
    const int tig  = lane & 3;

    const int m0 = blockIdx.x * 128;
    const int n0 = blockIdx.y * 128;

    const int li = lane >> 3;
    const int lr = lane & 7;
    const uint32_t aoffl = (uint32_t)(((li & 1) * 8 + lr) * RPITCH + (li >> 1) * 16);
    const uint32_t boffl = (uint32_t)(((li >> 1) * 8 + lr) * RPITCH + (li & 1) * 16);

    const int r0   = tid >> 1;
    const int half = tid & 1;
    const uint32_t sdst = (uint32_t)(r0 * RPITCH + half * 16);
    const __half* pA  = A  + (size_t)(m0 + r0) * K + half * 8;
    const __half* pWh = Wh + (size_t)(n0 + r0) * K + half * 8;
    const __half* pWl = (TERMS == 2) ? (Wl + (size_t)(n0 + r0) * K + half * 8) : nullptr;

    const int nkt = K >> 4;

    float c[2][8][4];
#pragma unroll
    for (int mt = 0; mt < 2; mt++)
#pragma unroll
        for (int nt = 0; nt < 8; nt++)
#pragma unroll
            for (int i = 0; i < 4; i++) c[mt][nt][i] = 0.f;

#pragma unroll
    for (int s = 0; s < 3; s++) {
        uint32_t b = sbase + (uint32_t)s * STAGEB + sdst;
        int ko = s * 16;
        cp_async16(b,            pA  + ko);
        cp_async16(b + ARRB,     pWh + ko);
        if (TERMS == 2) cp_async16(b + 2 * ARRB, pWl + ko);
        CP_COMMIT();
    }

    for (int kt = 0; kt < nkt; kt++) {
        CP_WAIT2();
        __syncthreads();

        uint32_t sb = sbase + (uint32_t)(kt & 3) * STAGEB;

        uint32_t a[2][4];
#pragma unroll
        for (int mt = 0; mt < 2; mt++) {
            uint32_t aaddr = sb + (uint32_t)((wm + mt * 16) * RPITCH) + aoffl;
            LDSM4(a[mt], aaddr);
        }
#pragma unroll
        for (int nh = 0; nh < 2; nh++) {
            uint32_t wh[2][4], wl[2][4];
#pragma unroll
            for (int pq = 0; pq < 2; pq++) {
                uint32_t baddr = sb + ARRB +
                                 (uint32_t)((wn + nh * 32 + pq * 16) * RPITCH) + boffl;
                LDSM4(wh[pq], baddr);
                if (TERMS == 2) LDSM4(wl[pq], baddr + ARRB);
            }
#pragma unroll
            for (int mt = 0; mt < 2; mt++)
#pragma unroll
                for (int pq = 0; pq < 2; pq++)
#pragma unroll
                    for (int h = 0; h < 2; h++)
                        mma_f16(c[mt][nh * 4 + pq * 2 + h], a[mt], &wh[pq][h * 2]);
            if (TERMS == 2) {
#pragma unroll
                for (int mt = 0; mt < 2; mt++)
#pragma unroll
                    for (int pq = 0; pq < 2; pq++)
#pragma unroll
                        for (int h = 0; h < 2; h++)
                            mma_f16(c[mt][nh * 4 + pq * 2 + h], a[mt], &wl[pq][h * 2]);
            }
        }

        if (kt + 3 < nkt) {
            uint32_t b = sbase + (uint32_t)((kt + 3) & 3) * STAGEB + sdst;
            int ko = (kt + 3) * 16;
            cp_async16(b,            pA  + ko);
            cp_async16(b + ARRB,     pWh + ko);
            if (TERMS == 2) cp_async16(b + 2 * ARRB, pWl + ko);
        }
        CP_COMMIT();
    }

    if (actout) {
#pragma unroll
        for (int mt = 0; mt < 2; mt++) {
            int row = m0 + wm + mt * 16 + grp;
#pragma unroll
            for (int nt = 0; nt < 8; nt++) {
                int col = n0 + wn + nt * 8 + tig * 2;
                int pair = col >> 1;
                {
                    float g = c[mt][nt][0] * WINV;
                    float u = c[mt][nt][1] * WINV;
                    float sig = 1.0f / (1.0f + __expf(-g));
                    actout[(size_t)row * Ic + pair] = __float2half_rn(g * sig * u);
                }
                {
                    float g = c[mt][nt][2] * WINV;
                    float u = c[mt][nt][3] * WINV;
                    float sig = 1.0f / (1.0f + __expf(-g));
                    actout[(size_t)(row + 8) * Ic + pair] = __float2half_rn(g * sig * u);
                }
            }
        }
    } else if (qh) {
        // QKV mode: RoPE via table + split-fp16 scatter.
        int head64 = n0 + wn;
#pragma unroll
        for (int mt = 0; mt < 2; mt++) {
#pragma unroll
            for (int r = 0; r < 2; r++) {
                int tok = m0 + wm + mt * 16 + grp + r * 8;
                int bb = tok / Sc;
                int ss = tok - bb * Sc;
                const float2* rt = g_rope + ss * 32;
                if (head64 < NHc * HDc) {
                    int head = head64 >> 6;
                    size_t base = (size_t)tok * Hc + head * HDc;
#pragma unroll
                    for (int nt = 0; nt < 4; nt++) {
#pragma unroll
                        for (int e = 0; e < 2; e++) {
                            int j = nt * 8 + tig * 2 + e;
                            float x1 = c[mt][nt][r * 2 + e] * WINV;
                            float x2 = c[mt][nt + 4][r * 2 + e] * WINV;
                            float2 cs = rt[j];
                            float r1 = (x1 * cs.x - x2 * cs.y) * 0.125f;
                            float r2 = (x2 * cs.x + x1 * cs.y) * 0.125f;
                            __half h1, l1, h2, l2;
                            split2h(r1, h1, l1);
                            split2h(r2, h2, l2);
                            qh[base + j] = h1;       ql[base + j] = l1;
                            qh[base + j + 32] = h2;  ql[base + j + 32] = l2;
                        }
                    }
                } else if (head64 < (NHc + NKVc) * HDc) {
                    int hk = (head64 - NHc * HDc) >> 6;
                    size_t base = (((size_t)(bb * NKVc + hk)) * Sc + ss) * HDc;
#pragma unroll
                    for (int nt = 0; nt < 4; nt++) {
#pragma unroll
                        for (int e = 0; e < 2; e++) {
                            int j = nt * 8 + tig * 2 + e;
                            float x1 = c[mt][nt][r * 2 + e] * WINV;
                            float x2 = c[mt][nt + 4][r * 2 + e] * WINV;
                            float2 cs = rt[j];
                            float r1 = x1 * cs.x - x2 * cs.y;
                            float r2 = x2 * cs.x + x1 * cs.y;
                            __half h1, l1, h2, l2;
                            split2h(r1, h1, l1);
                            split2h(r2, h2, l2);
                            kh[base + j] = h1;       kl[base + j] = l1;
                            kh[base + j + 32] = h2;  kl[base + j + 32] = l2;
                        }
                    }
                } else {
                    int hv = (head64 - (NHc + NKVc) * HDc) >> 6;
                    size_t base = (((size_t)(bb * NKVc + hv)) * Sc + ss) * HDc;
#pragma unroll
                    for (int nt = 0; nt < 8; nt++) {
#pragma unroll
                        for (int e = 0; e < 2; e++) {
                            int d = nt * 8 + tig * 2 + e;
                            float v = c[mt][nt][r * 2 + e] * WINV;
                            __half h1, l1;
                            split2h(v, h1, l1);
                            vh[base + d] = h1;  vl[base + d] = l1;
                        }
                    }
                }
            }
        }
    } else {
#pragma unroll
        for (int mt = 0; mt < 2; mt++) {
            int row = m0 + wm + mt * 16 + grp;
#pragma unroll
            for (int nt = 0; nt < 8; nt++) {
                int col = n0 + wn + nt * 8 + tig * 2;
                size_t i0 = (size_t)row * N + col;
                size_t i1 = (size_t)(row + 8) * N + col;
                float2 v0 = make_float2(c[mt][nt][0] * WINV, c[mt][nt][1] * WINV);
                float2 v1 = make_float2(c[mt][nt][2] * WINV, c[mt][nt][3] * WINV);
                if (addend) {
                    float2 a0 = *(const float2*)(addend + i0);
                    float2 a1 = *(const float2*)(addend + i1);
                    v0.x += a0.x; v0.y += a0.y;
                    v1.x += a1.x; v1.y += a1.y;
                }
                *(float2*)(C + i0) = v0;
                *(float2*)(C + i1) = v1;
            }
        }
    }
}

// ---------------------------------------------------------------------------
// Embedding gather
// ---------------------------------------------------------------------------
__global__ void embed_kernel(const int* __restrict__ ids,
                             const float* __restrict__ embed,
                             float* __restrict__ res) {
    int t = blockIdx.x;
    int id = ids[t];
    const float4* src = (const float4*)(embed + (size_t)id * Hc);
    float4* dst = (float4*)(res + (size_t)t * Hc);
    for (int i = threadIdx.x; i < Hc / 4; i += blockDim.x)
        dst[i] = src[i];
}

// ---------------------------------------------------------------------------
// RMSNorm. Output fp32 and/or fp16.
// ---------------------------------------------------------------------------
__global__ void addnorm_kernel(const float* __restrict__ res,
                               const float* __restrict__ w,
                               float* __restrict__ outf,
                               __half* __restrict__ oh) {
    int t = blockIdx.x;
    int tid = threadIdx.x;
    const float* rp = res + (size_t)t * Hc;
    float vals[8];
    float ss = 0.f;
#pragma unroll
    for (int i = 0; i < 8; i++) {
        int idx = tid + i * 256;
        float v = rp[idx];
        vals[i] = v;
        ss += v * v;
    }
    __shared__ float warp_s[8];
#pragma unroll
    for (int off = 16; off > 0; off >>= 1)
        ss += __shfl_down_sync(0xffffffff, ss, off);
    if ((tid & 31) == 0) warp_s[tid >> 5] = ss;
    __syncthreads();
    if (tid < 8) {
        float v = warp_s[tid];
#pragma unroll
        for (int off = 4; off > 0; off >>= 1)
            v += __shfl_down_sync(0xff, v, off);
        if (tid == 0) warp_s[0] = v;
    }
    __syncthreads();
    float inv = rsqrtf(warp_s[0] * (1.0f / Hc) + EPSc);
#pragma unroll
    for (int i = 0; i < 8; i++) {
        int idx = tid + i * 256;
        float o = vals[i] * inv * w[idx];
        if (outf) outf[(size_t)t * Hc + idx] = o;
        if (oh)   oh[(size_t)t * Hc + idx] = __float2half_rn(o);
    }
}

// ---------------------------------------------------------------------------
// Flash attention on fp16 MMA. One block = 64 queries of one (b, head),
// 4 warps x 16 rows, 128 threads. QK: 3-term split (exact).
// PV: P 2-term x V 2-term (3 terms). Heavy blocks first.
// ---------------------------------------------------------------------------
#define FPITCHB 144
#define FARR    (64 * FPITCHB)
#define FBUF    (4 * FARR)
#define FLASH_SMEM (2 * FBUF)

__global__ void __launch_bounds__(128)
flash_mma(const __half* __restrict__ qhg, const __half* __restrict__ qlg,
          const __half* __restrict__ khg, const __half* __restrict__ klg,
          const __half* __restrict__ vhg, const __half* __restrict__ vlg,
          __half* __restrict__ aout) {
    extern __shared__ char smraw[];
    uint32_t sbase = smem_u32(smraw);

    const int qb = (int)gridDim.x - 1 - (int)blockIdx.x;   // heavy-first
    const int h  = blockIdx.y;
    const int b  = blockIdx.z;
    const int hkv = h / (NHc / NKVc);
    const int tid = threadIdx.x;
    const int w   = tid >> 5;
    const int lane = tid & 31;
    const int grp = lane >> 2;
    const int tig = lane & 3;
    const int li = lane >> 3;
    const int lr = lane & 7;
    const uint32_t boffl = (uint32_t)(((li >> 1) * 8 + lr) * FPITCHB + (li & 1) * 16);
    const uint32_t voffl = (uint32_t)(((li & 1) * 8 + lr) * FPITCHB + (li >> 1) * 16);

    uint32_t qfh[4][4], qfl[4][4];
    {
        int row0 = b * Sc + qb * 64 + w * 16 + grp;
#pragma unroll
        for (int kt = 0; kt < 4; kt++) {
#pragma unroll
            for (int i = 0; i < 4; i++) {
                int row = row0 + (i & 1) * 8;
                int col = h * HDc + kt * 16 + (i >> 1) * 8 + tig * 2;
                qfh[kt][i] = *(const uint32_t*)&qhg[(size_t)row * Hc + col];
                qfl[kt][i] = *(const uint32_t*)&qlg[(size_t)row * Hc + col];
            }
        }
    }

    float o[8][4];
#pragma unroll
    for (int dn = 0; dn < 8; dn++)
#pragma unroll
        for (int i = 0; i < 4; i++) o[dn][i] = 0.f;
    float m0 = -1e30f, m1 = -1e30f, l0 = 0.f, l1 = 0.f;

    const size_t kvbase = ((size_t)(b * NKVc + hkv)) * Sc;

    {
        uint32_t bb = sbase;
#pragma unroll
        for (int i = 0; i < 4; i++) {
            int chunk = tid + i * 128;
            int r = chunk >> 3, cc = chunk & 7;
            uint32_t so = (uint32_t)(r * FPITCHB + cc * 16);
            size_t go = (kvbase + r) * HDc + cc * 8;
            cp_async16(bb + so,            khg + go);
            cp_async16(bb + FARR + so,     klg + go);
            cp_async16(bb + 2 * FARR + so, vhg + go);
            cp_async16(bb + 3 * FARR + so, vlg + go);
        }
        CP_COMMIT();
    }

    for (int kb = 0; kb <= qb; kb++) {
        CP_WAIT0();
        __syncthreads();

        if (kb + 1 <= qb) {
            uint32_t bb = sbase + (uint32_t)((kb + 1) & 1) * FBUF;
#pragma unroll
            for (int i = 0; i < 4; i++) {
                int chunk = tid + i * 128;
                int r = chunk >> 3, cc = chunk & 7;
                uint32_t so = (uint32_t)(r * FPITCHB + cc * 16);
                size_t go = (kvbase + (kb + 1) * 64 + r) * HDc + cc * 8;
                cp_async16(bb + so,            khg + go);
                cp_async16(bb + FARR + so,     klg + go);
                cp_async16(bb + 2 * FARR + so, vhg + go);
                cp_async16(bb + 3 * FARR + so, vlg + go);
            }
            CP_COMMIT();
        }

        uint32_t sb = sbase + (uint32_t)(kb & 1) * FBUF;

        float s[8][4];
#pragma unroll
        for (int nt = 0; nt < 8; nt++)
#pragma unroll
            for (int i = 0; i < 4; i++) s[nt][i] = 0.f;

#pragma unroll
        for (int kt = 0; kt < 4; kt++) {
            uint32_t kfh[4][4], kfl[4][4];
#pragma unroll
            for (int kg = 0; kg < 4; kg++) {
                uint32_t addr = sb + (uint32_t)(kg * 16 * FPITCHB) + (uint32_t)(kt * 32) + boffl;
                LDSM4(kfh[kg], addr);
                LDSM4(kfl[kg], addr + FARR);
            }
#pragma unroll
            for (int kg = 0; kg < 4; kg++)
#pragma unroll
                for (int hh = 0; hh < 2; hh++)
                    mma_f16(s[kg * 2 + hh], qfh[kt], &kfh[kg][hh * 2]);
#pragma unroll
            for (int kg = 0; kg < 4; kg++)
#pragma unroll
                for (int hh = 0; hh < 2; hh++)
                    mma_f16(s[kg * 2 + hh], qfh[kt], &kfl[kg][hh * 2]);
#pragma unroll
            for (int kg = 0; kg < 4; kg++)
#pragma unroll
                for (int hh = 0; hh < 2; hh++)
                    mma_f16(s[kg * 2 + hh], qfl[kt], &kfh[kg][hh * 2]);
        }

        if (kb == qb) {
            int rl0 = w * 16 + grp;
            int rl1 = rl0 + 8;
#pragma unroll
            for (int nt = 0; nt < 8; nt++) {
                int cl = nt * 8 + tig * 2;
                if (cl     > rl0) s[nt][0] = -1e30f;
                if (cl + 1 > rl0) s[nt][1] = -1e30f;
                if (cl     > rl1) s[nt][2] = -1e30f;
                if (cl + 1 > rl1) s[nt][3] = -1e30f;
            }
        }

        {
            float mx0 = -1e30f, mx1 = -1e30f;
#pragma unroll
            for (int nt = 0; nt < 8; nt++) {
                mx0 = fmaxf(mx0, fmaxf(s[nt][0], s[nt][1]));
                mx1 = fmaxf(mx1, fmaxf(s[nt][2], s[nt][3]));
            }
            mx0 = fmaxf(mx0, __shfl_xor_sync(0xffffffffu, mx0, 1));
            mx0 = fmaxf(mx0, __shfl_xor_sync(0xffffffffu, mx0, 2));
            mx1 = fmaxf(mx1, __shfl_xor_sync(0xffffffffu, mx1, 1));
            mx1 = fmaxf(mx1, __shfl_xor_sync(0xffffffffu, mx1, 2));
            float mn0 = fmaxf(m0, mx0);
            float mn1 = fmaxf(m1, mx1);
            float a0 = __expf(m0 - mn0);
            float a1 = __expf(m1 - mn1);
            float su0 = 0.f, su1 = 0.f;
#pragma unroll
            for (int nt = 0; nt < 8; nt++) {
                s[nt][0] = __expf(s[nt][0] - mn0); su0 += s[nt][0];
                s[nt][1] = __expf(s[nt][1] - mn0); su0 += s[nt][1];
                s[nt][2] = __expf(s[nt][2] - mn1); su1 += s[nt][2];
                s[nt][3] = __expf(s[nt][3] - mn1); su1 += s[nt][3];
            }
            su0 += __shfl_xor_sync(0xffffffffu, su0, 1);
            su0 += __shfl_xor_sync(0xffffffffu, su0, 2);
            su1 += __shfl_xor_sync(0xffffffffu, su1, 1);
            su1 += __shfl_xor_sync(0xffffffffu, su1, 2);
            l0 = l0 * a0 + su0;
            l1 = l1 * a1 + su1;
            m0 = mn0;
            m1 = mn1;
#pragma unroll
            for (int dn = 0; dn < 8; dn++) {
                o[dn][0] *= a0; o[dn][1] *= a0;
                o[dn][2] *= a1; o[dn][3] *= a1;
            }
        }

        // PV with exact 2-term P: Phi*Vhi + Phi*Vlo + Plo*Vhi
#pragma unroll
        for (int kt = 0; kt < 4; kt++) {
            uint32_t ah[4], al[4];
#pragma unroll
            for (int q4 = 0; q4 < 4; q4++) {
                int nt = 2 * kt + (q4 >> 1);
                int bs = (q4 & 1) * 2;
                float p0 = s[nt][bs], p1 = s[nt][bs + 1];
                __half h0 = __float2half_rn(p0);
                __half h1v = __float2half_rn(p1);
                float lo0 = p0 - __half2float(h0);
                float lo1 = p1 - __half2float(h1v);
                __half2 hp; hp.x = h0; hp.y = h1v;
                ah[q4] = *(uint32_t*)&hp;
                al[q4] = packh2(lo0, lo1);
            }
            uint32_t vfh[4][4], vfl[4][4];
#pragma unroll
            for (int db = 0; db < 4; db++) {
                uint32_t addr = sb + 2 * FARR + (uint32_t)(kt * 16 * FPITCHB) + (uint32_t)(db * 32) + voffl;
                LDSM4T(vfh[db], addr);
                LDSM4T(vfl[db], addr + FARR);
            }
#pragma unroll
            for (int db = 0; db < 4; db++)
#pragma unroll
                for (int hh = 0; hh < 2; hh++)
                    mma_f16(o[db * 2 + hh], ah, &vfh[db][hh * 2]);
#pragma unroll
            for (int db = 0; db < 4; db++)
#pragma unroll
                for (int hh = 0; hh < 2; hh++)
                    mma_f16(o[db * 2 + hh], ah, &vfl[db][hh * 2]);
#pragma unroll
            for (int db = 0; db < 4; db++)
#pragma unroll
                for (int hh = 0; hh < 2; hh++)
                    mma_f16(o[db * 2 + hh], al, &vfh[db][hh * 2]);
        }
    }

    {
        float i0 = 1.0f / l0;
        float i1 = 1.0f / l1;
        size_t row0 = (size_t)(b * Sc + qb * 64 + w * 16 + grp);
#pragma unroll
        for (int dn = 0; dn < 8; dn++) {
            int col = h * HDc + dn * 8 + tig * 2;
            __half2 p0 = __floats2half2_rn(o[dn][0] * i0, o[dn][1] * i0);
            __half2 p1 = __floats2half2_rn(o[dn][2] * i1, o[dn][3] * i1);
            *(__half2*)&aout[row0 * Hc + col] = p0;
            *(__half2*)&aout[(row0 + 8) * Hc + col] = p1;
        }
    }
}

// ---------------------------------------------------------------------------
// Launch
// ---------------------------------------------------------------------------
extern "C" void kernel_launch(void* const* d_in, const int* in_sizes, int n_in,
                              void* d_out, int out_size) {
    const int*   input_ids = (const int*)d_in[0];
    const int*   positions = (const int*)d_in[1];
    const float* embed     = (const float*)d_in[2];
    const float* w_qkv     = (const float*)d_in[3];
    const float* w_o       = (const float*)d_in[4];
    const float* w_gate_up = (const float*)d_in[5];
    const float* w_down    = (const float*)d_in[6];
    const float* ln1_w     = (const float*)d_in[7];
    const float* ln2_w     = (const float*)d_in[8];
    const float* norm_w    = (const float*)d_in[9];
    float* out = (float*)d_out;

    float *res;
    __half *hn, *at, *ac, *wh, *wl, *qh, *ql, *kh, *kl, *vh, *vl;
    cudaGetSymbolAddress((void**)&res,  g_res);
    cudaGetSymbolAddress((void**)&hn,   g_hn);
    cudaGetSymbolAddress((void**)&at,   g_at);
    cudaGetSymbolAddress((void**)&ac,   g_ac);
    cudaGetSymbolAddress((void**)&wh,   g_wh);
    cudaGetSymbolAddress((void**)&wl,   g_wl);
    cudaGetSymbolAddress((void**)&qh,   g_qh);
    cudaGetSymbolAddress((void**)&ql,   g_ql);
    cudaGetSymbolAddress((void**)&kh,   g_kh);
    cudaGetSymbolAddress((void**)&kl,   g_kl);
    cudaGetSymbolAddress((void**)&vh,   g_vh);
    cudaGetSymbolAddress((void**)&vl,   g_vl);

    cudaFuncSetAttribute(flash_mma, cudaFuncAttributeMaxDynamicSharedMemorySize, FLASH_SMEM);
    cudaFuncSetAttribute(gemm_f16<2>, cudaFuncAttributeMaxDynamicSharedMemorySize, GEMM_SMEM);
    cudaFuncSetAttribute(gemm_f16<1>, cudaFuncAttributeMaxDynamicSharedMemorySize, GEMM_SMEM);

    prep_weights<<<2 * TILES_PER_LAYER, dim3(32, 8)>>>(
        w_qkv, w_o, w_gate_up, w_down, wh, wl);
    rope_table_kernel<<<Sc, 32>>>(positions);

    embed_kernel<<<Tc, 256>>>(input_ids, embed, res);

    for (int l = 0; l < Lc; l++) {
        __half* whl = wh + (size_t)l * WT_PER_L;
        __half* wll = wl + (size_t)l * WT_PER_L;

        addnorm_kernel<<<Tc, 256>>>(res, ln1_w + (size_t)l * Hc, nullptr, hn);

        // QKV projection with fused RoPE (table) + split-fp16 scatter
        gemm_f16<2><<<dim3(Tc / 128, QKVN / 128), 256, GEMM_SMEM>>>(
            hn, whl + WT_QKV_OFF, wll + WT_QKV_OFF, nullptr, nullptr, nullptr,
            qh, ql, kh, kl, vh, vl, Tc, QKVN, Hc);

        flash_mma<<<dim3(Sc / 64, NHc, Bc), 128, FLASH_SMEM>>>(
            qh, ql, kh, kl, vh, vl, at);

        gemm_f16<2><<<dim3(Tc / 128, Hc / 128), 256, GEMM_SMEM>>>(
            at, whl + WT_O_OFF, wll + WT_O_OFF, res, res, nullptr,
            nullptr, nullptr, nullptr, nullptr, nullptr, nullptr,
            Tc, Hc, Hc);

        addnorm_kernel<<<Tc, 256>>>(res, ln2_w + (size_t)l * Hc, nullptr, hn);

        gemm_f16<1><<<dim3(Tc / 128, GUN / 128), 256, GEMM_SMEM>>>(
            hn, whl + WT_GU_OFF, nullptr, nullptr, nullptr, ac,
            nullptr, nullptr, nullptr, nullptr, nullptr, nullptr,
            Tc, GUN, Hc);

        gemm_f16<1><<<dim3(Tc / 128, Hc / 128), 256, GEMM_SMEM>>>(
            ac, whl + WT_DN_OFF, nullptr, res, res, nullptr,
            nullptr, nullptr, nullptr, nullptr, nullptr, nullptr,
            Tc, Hc, Ic);
    }

    addnorm_kernel<<<Tc, 256>>>(res, norm_w, out, nullptr);
}

// round 15
// speedup vs baseline: 1.0190x; 1.0072x over previous
#include <cuda_runtime.h>
#include <cuda_fp16.h>
#include <math.h>
#include <stdint.h>

// ---------------------------------------------------------------------------
// Model constants
// ---------------------------------------------------------------------------
#define Lc 2
#define Hc 2048
#define NHc 32
#define NKVc 4
#define HDc 64
#define Ic 5632
#define Bc 2
#define Sc 1024
#define Tc (Bc * Sc)                   // 2048 tokens
#define QKVN ((NHc + 2 * NKVc) * HDc)  // 2560
#define GUN (2 * Ic)                   // 11264
#define EPSc 1e-5f
#define WSCALE 64.0f
#define WINV   0.015625f               // 1/64
#define ROPE_LT 0.2878231366f          // ln(10000)/32

// ---------------------------------------------------------------------------
// Scratch (static device globals; no allocation allowed)
// ---------------------------------------------------------------------------
__device__ float g_res [Tc * Hc];

// fp16 activations (GEMM A operands)
__device__ __half g_hn [Tc * Hc];
__device__ __half g_at [Tc * Hc];
__device__ __half g_ac [(size_t)Tc * Ic];

// split fp16 Q (pre-scaled by 0.125) and KV caches
__device__ __half g_qh [Tc * Hc];
__device__ __half g_ql [Tc * Hc];
__device__ __half g_kh [Bc * NKVc * Sc * HDc];
__device__ __half g_kl [Bc * NKVc * Sc * HDc];
__device__ __half g_vh [Bc * NKVc * Sc * HDc];
__device__ __half g_vl [Bc * NKVc * Sc * HDc];

// RoPE cos/sin table [seq][32]
__device__ float2 g_rope[Sc * 32];

// Transposed split weights (x64 scaled, fp16 hi+lo exact 2-term):
// per layer [qkv_t(QKVN,H) | o_t(H,H) | gu_t(GUN,H, gate/up interleaved) | down_t(H,I)]
#define WT_QKV_OFF 0
#define WT_O_OFF   ((size_t)QKVN * Hc)
#define WT_GU_OFF  (WT_O_OFF + (size_t)Hc * Hc)
#define WT_DN_OFF  (WT_GU_OFF + (size_t)GUN * Hc)
#define WT_PER_L   (WT_DN_OFF + (size_t)Hc * Ic)
__device__ __half g_wh[2 * WT_PER_L];
__device__ __half g_wl[2 * WT_PER_L];

// ---------------------------------------------------------------------------
// Helpers
// ---------------------------------------------------------------------------
__device__ __forceinline__ uint32_t smem_u32(const void* p) {
    uint32_t a;
    asm("{ .reg .u64 t; cvta.to.shared.u64 t, %1; cvt.u32.u64 %0, t; }"
        : "=r"(a) : "l"(p));
    return a;
}

__device__ __forceinline__ void cp_async16(uint32_t smem_addr, const void* gptr) {
    asm volatile("cp.async.cg.shared.global [%0], [%1], 16;"
                 :: "r"(smem_addr), "l"(gptr) : "memory");
}
#define CP_COMMIT() asm volatile("cp.async.commit_group;" ::: "memory")
#define CP_WAIT0()  asm volatile("cp.async.wait_group 0;" ::: "memory")
#define CP_WAIT2()  asm volatile("cp.async.wait_group 2;" ::: "memory")

__device__ __forceinline__ void mma_f16(float* d, const uint32_t* a, const uint32_t* b) {
    asm volatile(
        "mma.sync.aligned.m16n8k16.row.col.f32.f16.f16.f32 "
        "{%0,%1,%2,%3}, {%4,%5,%6,%7}, {%8,%9}, {%0,%1,%2,%3};"
        : "+f"(d[0]), "+f"(d[1]), "+f"(d[2]), "+f"(d[3])
        : "r"(a[0]), "r"(a[1]), "r"(a[2]), "r"(a[3]),
          "r"(b[0]), "r"(b[1]));
}

#define LDSM4(R, A) \
    asm volatile("ldmatrix.sync.aligned.m8n8.x4.shared.b16 {%0,%1,%2,%3}, [%4];" \
        : "=r"((R)[0]), "=r"((R)[1]), "=r"((R)[2]), "=r"((R)[3]) : "r"(A))

#define LDSM4T(R, A) \
    asm volatile("ldmatrix.sync.aligned.m8n8.x4.trans.shared.b16 {%0,%1,%2,%3}, [%4];" \
        : "=r"((R)[0]), "=r"((R)[1]), "=r"((R)[2]), "=r"((R)[3]) : "r"(A))

__device__ __forceinline__ void split2h(float x, __half& hi, __half& lo) {
    hi = __float2half_rn(x);
    lo = __float2half_rn(x - __half2float(hi));
}

__device__ __forceinline__ uint32_t packh2(float a, float b) {
    __half2 h = __floats2half2_rn(a, b);
    return *(uint32_t*)&h;
}

// ---------------------------------------------------------------------------
// RoPE table (bit-identical expressions to the fused-epilogue math)
// ---------------------------------------------------------------------------
__global__ void rope_table_kernel(const int* __restrict__ pos) {
    int s = blockIdx.x;
    int j = threadIdx.x;
    float p = (float)pos[s];
    float ang = p * __expf(-(float)j * ROPE_LT);
    g_rope[s * 32 + j] = make_float2(cosf(ang), sinf(ang));
}

// ---------------------------------------------------------------------------
// Fused weight prep: transpose + x64 scale + exact fp16 2-term split.
// gate_up destination rows interleaved (gate i -> 2i, up i -> 2i+1).
// ---------------------------------------------------------------------------
#define TILES_PER_LAYER 43008
__global__ void prep_weights(const float* __restrict__ wqkv,
                             const float* __restrict__ wo,
                             const float* __restrict__ wgu,
                             const float* __restrict__ wdn,
                             __half* __restrict__ wth,
                             __half* __restrict__ wtl) {
    __shared__ float tile[32][33];
    int bid = blockIdx.x;
    int l = 0;
    if (bid >= TILES_PER_LAYER) { l = 1; bid -= TILES_PER_LAYER; }
    size_t loff = (size_t)l * WT_PER_L;

    const float* src;
    __half *hi, *lo;
    int K, N;
    int gu_mode = 0;
    if (bid < 5120) {
        src = wqkv + (size_t)l * Hc * QKVN;
        hi = wth + loff + WT_QKV_OFF; lo = wtl + loff + WT_QKV_OFF;
        K = Hc; N = QKVN;
    } else if (bid < 9216) {
        bid -= 5120;
        src = wo + (size_t)l * Hc * Hc;
        hi = wth + loff + WT_O_OFF; lo = wtl + loff + WT_O_OFF;
        K = Hc; N = Hc;
    } else if (bid < 31744) {
        bid -= 9216;
        src = wgu + (size_t)l * Hc * GUN;
        hi = wth + loff + WT_GU_OFF; lo = wtl + loff + WT_GU_OFF;
        K = Hc; N = GUN;
        gu_mode = 1;
    } else {
        bid -= 31744;
        src = wdn + (size_t)l * Ic * Hc;
        hi = wth + loff + WT_DN_OFF; lo = wtl + loff + WT_DN_OFF;
        K = Ic; N = Hc;
    }
    int tilesX = N / 32;
    int nb = (bid % tilesX) * 32;
    int kb = (bid / tilesX) * 32;

#pragma unroll
    for (int i = threadIdx.y; i < 32; i += 8)
        tile[i][threadIdx.x] = src[(size_t)(kb + i) * N + nb + threadIdx.x];
    __syncthreads();
#pragma unroll
    for (int i = threadIdx.y; i < 32; i += 8) {
        float v = tile[threadIdx.x][i] * WSCALE;
        __half h, lv;
        split2h(v, h, lv);
        int col = nb + i;
        if (gu_mode) col = (col < Ic) ? (2 * col) : (2 * (col - Ic) + 1);
        size_t idx = (size_t)col * K + kb + threadIdx.x;
        hi[idx] = h;
        lo[idx] = lv;
    }
}

// ---------------------------------------------------------------------------
// fp16 GEMM, templated on weight TERMS (2 = exact split, 1 = fp16 weights).
// Epilogue modes:
//   actout != nullptr : interleaved (gate,up) cols -> silu(g)*u fp16
//   qh     != nullptr : QKV mode -> RoPE (table) + split-fp16 scatter
//   else              : fp32 C (+ optional addend)
// ---------------------------------------------------------------------------
#define RPITCH 48
#define ARRB   (128 * RPITCH)
#define STAGEB (3 * ARRB)
#define GEMM_SMEM (4 * STAGEB)

template <int TERMS>
__global__ void __launch_bounds__(256, 2)
gemm_f16(const __half* __restrict__ A,
         const __half* __restrict__ Wh,
         const __half* __restrict__ Wl,
         float* __restrict__ C, const float* __restrict__ addend,
         __half* __restrict__ actout,
         __half* __restrict__ qh, __half* __restrict__ ql,
         __half* __restrict__ kh, __half* __restrict__ kl,
         __half* __restrict__ vh, __half* __restrict__ vl,
         int M, int N, int K) {
    extern __shared__ char smraw[];
    uint32_t sbase = smem_u32(smraw);

    const int tid  = threadIdx.x;
    const int warp = tid >> 5;
    const int lane = tid & 31;
    const int wm   = (warp >> 1) * 32;
    const int wn   = (warp & 1) * 64;
    const int grp  = lane >> 2;
    const int tig  = lane & 3;

    const int m0 = blockIdx.x * 128;
    const int n0 = blockIdx.y * 128;

    const int li = lane >> 3;
    const int lr = lane & 7;
    const uint32_t aoffl = (uint32_t)(((li & 1) * 8 + lr) * RPITCH + (li >> 1) * 16);
    const uint32_t boffl = (uint32_t)(((li >> 1) * 8 + lr) * RPITCH + (li & 1) * 16);

    const int r0   = tid >> 1;
    const int half = tid & 1;
    const uint32_t sdst = (uint32_t)(r0 * RPITCH + half * 16);
    const __half* pA  = A  + (size_t)(m0 + r0) * K + half * 8;
    const __half* pWh = Wh + (size_t)(n0 + r0) * K + half * 8;
    const __half* pWl = (TERMS == 2) ? (Wl + (size_t)(n0 + r0) * K + half * 8) : nullptr;

    const int nkt = K >> 4;

    float c[2][8][4];
#pragma unroll
    for (int mt = 0; mt < 2; mt++)
#pragma unroll
        for (int nt = 0; nt < 8; nt++)
#pragma unroll
            for (int i = 0; i < 4; i++) c[mt][nt][i] = 0.f;

#pragma unroll
    for (int s = 0; s < 3; s++) {
        uint32_t b = sbase + (uint32_t)s * STAGEB + sdst;
        int ko = s * 16;
        cp_async16(b,            pA  + ko);
        cp_async16(b + ARRB,     pWh + ko);
        if (TERMS == 2) cp_async16(b + 2 * ARRB, pWl + ko);
        CP_COMMIT();
    }

    for (int kt = 0; kt < nkt; kt++) {
        CP_WAIT2();
        __syncthreads();

        uint32_t sb = sbase + (uint32_t)(kt & 3) * STAGEB;

        uint32_t a[2][4];
#pragma unroll
        for (int mt = 0; mt < 2; mt++) {
            uint32_t aaddr = sb + (uint32_t)((wm + mt * 16) * RPITCH) + aoffl;
            LDSM4(a[mt], aaddr);
        }
#pragma unroll
        for (int nh = 0; nh < 2; nh++) {
            uint32_t wh[2][4], wl[2][4];
#pragma unroll
            for (int pq = 0; pq < 2; pq++) {
                uint32_t baddr = sb + ARRB +
                                 (uint32_t)((wn + nh * 32 + pq * 16) * RPITCH) + boffl;
                LDSM4(wh[pq], baddr);
                if (TERMS == 2) LDSM4(wl[pq], baddr + ARRB);
            }
#pragma unroll
            for (int mt = 0; mt < 2; mt++)
#pragma unroll
                for (int pq = 0; pq < 2; pq++)
#pragma unroll
                    for (int h = 0; h < 2; h++)
                        mma_f16(c[mt][nh * 4 + pq * 2 + h], a[mt], &wh[pq][h * 2]);
            if (TERMS == 2) {
#pragma unroll
                for (int mt = 0; mt < 2; mt++)
#pragma unroll
                    for (int pq = 0; pq < 2; pq++)
#pragma unroll
                        for (int h = 0; h < 2; h++)
                            mma_f16(c[mt][nh * 4 + pq * 2 + h], a[mt], &wl[pq][h * 2]);
            }
        }

        if (kt + 3 < nkt) {
            uint32_t b = sbase + (uint32_t)((kt + 3) & 3) * STAGEB + sdst;
            int ko = (kt + 3) * 16;
            cp_async16(b,            pA  + ko);
            cp_async16(b + ARRB,     pWh + ko);
            if (TERMS == 2) cp_async16(b + 2 * ARRB, pWl + ko);
        }
        CP_COMMIT();
    }

    if (actout) {
#pragma unroll
        for (int mt = 0; mt < 2; mt++) {
            int row = m0 + wm + mt * 16 + grp;
#pragma unroll
            for (int nt = 0; nt < 8; nt++) {
                int col = n0 + wn + nt * 8 + tig * 2;
                int pair = col >> 1;
                {
                    float g = c[mt][nt][0] * WINV;
                    float u = c[mt][nt][1] * WINV;
                    float sig = 1.0f / (1.0f + __expf(-g));
                    actout[(size_t)row * Ic + pair] = __float2half_rn(g * sig * u);
                }
                {
                    float g = c[mt][nt][2] * WINV;
                    float u = c[mt][nt][3] * WINV;
                    float sig = 1.0f / (1.0f + __expf(-g));
                    actout[(size_t)(row + 8) * Ic + pair] = __float2half_rn(g * sig * u);
                }
            }
        }
    } else if (qh) {
        // QKV mode: RoPE via table + split-fp16 scatter.
        int head64 = n0 + wn;
#pragma unroll
        for (int mt = 0; mt < 2; mt++) {
#pragma unroll
            for (int r = 0; r < 2; r++) {
                int tok = m0 + wm + mt * 16 + grp + r * 8;
                int bb = tok / Sc;
                int ss = tok - bb * Sc;
                const float2* rt = g_rope + ss * 32;
                if (head64 < NHc * HDc) {
                    int head = head64 >> 6;
                    size_t base = (size_t)tok * Hc + head * HDc;
#pragma unroll
                    for (int nt = 0; nt < 4; nt++) {
#pragma unroll
                        for (int e = 0; e < 2; e++) {
                            int j = nt * 8 + tig * 2 + e;
                            float x1 = c[mt][nt][r * 2 + e] * WINV;
                            float x2 = c[mt][nt + 4][r * 2 + e] * WINV;
                            float2 cs = rt[j];
                            float r1 = (x1 * cs.x - x2 * cs.y) * 0.125f;
                            float r2 = (x2 * cs.x + x1 * cs.y) * 0.125f;
                            __half h1, l1, h2, l2;
                            split2h(r1, h1, l1);
                            split2h(r2, h2, l2);
                            qh[base + j] = h1;       ql[base + j] = l1;
                            qh[base + j + 32] = h2;  ql[base + j + 32] = l2;
                        }
                    }
                } else if (head64 < (NHc + NKVc) * HDc) {
                    int hk = (head64 - NHc * HDc) >> 6;
                    size_t base = (((size_t)(bb * NKVc + hk)) * Sc + ss) * HDc;
#pragma unroll
                    for (int nt = 0; nt < 4; nt++) {
#pragma unroll
                        for (int e = 0; e < 2; e++) {
                            int j = nt * 8 + tig * 2 + e;
                            float x1 = c[mt][nt][r * 2 + e] * WINV;
                            float x2 = c[mt][nt + 4][r * 2 + e] * WINV;
                            float2 cs = rt[j];
                            float r1 = x1 * cs.x - x2 * cs.y;
                            float r2 = x2 * cs.x + x1 * cs.y;
                            __half h1, l1, h2, l2;
                            split2h(r1, h1, l1);
                            split2h(r2, h2, l2);
                            kh[base + j] = h1;       kl[base + j] = l1;
                            kh[base + j + 32] = h2;  kl[base + j + 32] = l2;
                        }
                    }
                } else {
                    int hv = (head64 - (NHc + NKVc) * HDc) >> 6;
                    size_t base = (((size_t)(bb * NKVc + hv)) * Sc + ss) * HDc;
#pragma unroll
                    for (int nt = 0; nt < 8; nt++) {
#pragma unroll
                        for (int e = 0; e < 2; e++) {
                            int d = nt * 8 + tig * 2 + e;
                            float v = c[mt][nt][r * 2 + e] * WINV;
                            __half h1, l1;
                            split2h(v, h1, l1);
                            vh[base + d] = h1;  vl[base + d] = l1;
                        }
                    }
                }
            }
        }
    } else {
#pragma unroll
        for (int mt = 0; mt < 2; mt++) {
            int row = m0 + wm + mt * 16 + grp;
#pragma unroll
            for (int nt = 0; nt < 8; nt++) {
                int col = n0 + wn + nt * 8 + tig * 2;
                size_t i0 = (size_t)row * N + col;
                size_t i1 = (size_t)(row + 8) * N + col;
                float2 v0 = make_float2(c[mt][nt][0] * WINV, c[mt][nt][1] * WINV);
                float2 v1 = make_float2(c[mt][nt][2] * WINV, c[mt][nt][3] * WINV);
                if (addend) {
                    float2 a0 = *(const float2*)(addend + i0);
                    float2 a1 = *(const float2*)(addend + i1);
                    v0.x += a0.x; v0.y += a0.y;
                    v1.x += a1.x; v1.y += a1.y;
                }
                *(float2*)(C + i0) = v0;
                *(float2*)(C + i1) = v1;
            }
        }
    }
}

// ---------------------------------------------------------------------------
// Embedding gather
// ---------------------------------------------------------------------------
__global__ void embed_kernel(const int* __restrict__ ids,
                             const float* __restrict__ embed,
                             float* __restrict__ res) {
    int t = blockIdx.x;
    int id = ids[t];
    const float4* src = (const float4*)(embed + (size_t)id * Hc);
    float4* dst = (float4*)(res + (size_t)t * Hc);
    for (int i = threadIdx.x; i < Hc / 4; i += blockDim.x)
        dst[i] = src[i];
}

// ---------------------------------------------------------------------------
// RMSNorm. Output fp32 and/or fp16.
// ---------------------------------------------------------------------------
__global__ void addnorm_kernel(const float* __restrict__ res,
                               const float* __restrict__ w,
                               float* __restrict__ outf,
                               __half* __restrict__ oh) {
    int t = blockIdx.x;
    int tid = threadIdx.x;
    const float* rp = res + (size_t)t * Hc;
    float vals[8];
    float ss = 0.f;
#pragma unroll
    for (int i = 0; i < 8; i++) {
        int idx = tid + i * 256;
        float v = rp[idx];
        vals[i] = v;
        ss += v * v;
    }
    __shared__ float warp_s[8];
#pragma unroll
    for (int off = 16; off > 0; off >>= 1)
        ss += __shfl_down_sync(0xffffffff, ss, off);
    if ((tid & 31) == 0) warp_s[tid >> 5] = ss;
    __syncthreads();
    if (tid < 8) {
        float v = warp_s[tid];
#pragma unroll
        for (int off = 4; off > 0; off >>= 1)
            v += __shfl_down_sync(0xff, v, off);
        if (tid == 0) warp_s[0] = v;
    }
    __syncthreads();
    float inv = rsqrtf(warp_s[0] * (1.0f / Hc) + EPSc);
#pragma unroll
    for (int i = 0; i < 8; i++) {
        int idx = tid + i * 256;
        float o = vals[i] * inv * w[idx];
        if (outf) outf[(size_t)t * Hc + idx] = o;
        if (oh)   oh[(size_t)t * Hc + idx] = __float2half_rn(o);
    }
}

// ---------------------------------------------------------------------------
// Flash attention on fp16 MMA. One block = 64 queries of one (b, head),
// 4 warps x 16 rows, 128 threads. QK: 3-term split (exact).
// PV: P fp16 x V 2-term split (2 terms). Heavy blocks first.
// ---------------------------------------------------------------------------
#define FPITCHB 144
#define FARR    (64 * FPITCHB)
#define FBUF    (4 * FARR)
#define FLASH_SMEM (2 * FBUF)

__global__ void __launch_bounds__(128)
flash_mma(const __half* __restrict__ qhg, const __half* __restrict__ qlg,
          const __half* __restrict__ khg, const __half* __restrict__ klg,
          const __half* __restrict__ vhg, const __half* __restrict__ vlg,
          __half* __restrict__ aout) {
    extern __shared__ char smraw[];
    uint32_t sbase = smem_u32(smraw);

    const int qb = (int)gridDim.x - 1 - (int)blockIdx.x;   // heavy-first
    const int h  = blockIdx.y;
    const int b  = blockIdx.z;
    const int hkv = h / (NHc / NKVc);
    const int tid = threadIdx.x;
    const int w   = tid >> 5;
    const int lane = tid & 31;
    const int grp = lane >> 2;
    const int tig = lane & 3;
    const int li = lane >> 3;
    const int lr = lane & 7;
    const uint32_t boffl = (uint32_t)(((li >> 1) * 8 + lr) * FPITCHB + (li & 1) * 16);
    const uint32_t voffl = (uint32_t)(((li & 1) * 8 + lr) * FPITCHB + (li >> 1) * 16);

    uint32_t qfh[4][4], qfl[4][4];
    {
        int row0 = b * Sc + qb * 64 + w * 16 + grp;
#pragma unroll
        for (int kt = 0; kt < 4; kt++) {
#pragma unroll
            for (int i = 0; i < 4; i++) {
                int row = row0 + (i & 1) * 8;
                int col = h * HDc + kt * 16 + (i >> 1) * 8 + tig * 2;
                qfh[kt][i] = *(const uint32_t*)&qhg[(size_t)row * Hc + col];
                qfl[kt][i] = *(const uint32_t*)&qlg[(size_t)row * Hc + col];
            }
        }
    }

    float o[8][4];
#pragma unroll
    for (int dn = 0; dn < 8; dn++)
#pragma unroll
        for (int i = 0; i < 4; i++) o[dn][i] = 0.f;
    float m0 = -1e30f, m1 = -1e30f, l0 = 0.f, l1 = 0.f;

    const size_t kvbase = ((size_t)(b * NKVc + hkv)) * Sc;

    {
        uint32_t bb = sbase;
#pragma unroll
        for (int i = 0; i < 4; i++) {
            int chunk = tid + i * 128;
            int r = chunk >> 3, cc = chunk & 7;
            uint32_t so = (uint32_t)(r * FPITCHB + cc * 16);
            size_t go = (kvbase + r) * HDc + cc * 8;
            cp_async16(bb + so,            khg + go);
            cp_async16(bb + FARR + so,     klg + go);
            cp_async16(bb + 2 * FARR + so, vhg + go);
            cp_async16(bb + 3 * FARR + so, vlg + go);
        }
        CP_COMMIT();
    }

    for (int kb = 0; kb <= qb; kb++) {
        CP_WAIT0();
        __syncthreads();

        if (kb + 1 <= qb) {
            uint32_t bb = sbase + (uint32_t)((kb + 1) & 1) * FBUF;
#pragma unroll
            for (int i = 0; i < 4; i++) {
                int chunk = tid + i * 128;
                int r = chunk >> 3, cc = chunk & 7;
                uint32_t so = (uint32_t)(r * FPITCHB + cc * 16);
                size_t go = (kvbase + (kb + 1) * 64 + r) * HDc + cc * 8;
                cp_async16(bb + so,            khg + go);
                cp_async16(bb + FARR + so,     klg + go);
                cp_async16(bb + 2 * FARR + so, vhg + go);
                cp_async16(bb + 3 * FARR + so, vlg + go);
            }
            CP_COMMIT();
        }

        uint32_t sb = sbase + (uint32_t)(kb & 1) * FBUF;

        float s[8][4];
#pragma unroll
        for (int nt = 0; nt < 8; nt++)
#pragma unroll
            for (int i = 0; i < 4; i++) s[nt][i] = 0.f;

#pragma unroll
        for (int kt = 0; kt < 4; kt++) {
            uint32_t kfh[4][4], kfl[4][4];
#pragma unroll
            for (int kg = 0; kg < 4; kg++) {
                uint32_t addr = sb + (uint32_t)(kg * 16 * FPITCHB) + (uint32_t)(kt * 32) + boffl;
                LDSM4(kfh[kg], addr);
                LDSM4(kfl[kg], addr + FARR);
            }
#pragma unroll
            for (int kg = 0; kg < 4; kg++)
#pragma unroll
                for (int hh = 0; hh < 2; hh++)
                    mma_f16(s[kg * 2 + hh], qfh[kt], &kfh[kg][hh * 2]);
#pragma unroll
            for (int kg = 0; kg < 4; kg++)
#pragma unroll
                for (int hh = 0; hh < 2; hh++)
                    mma_f16(s[kg * 2 + hh], qfh[kt], &kfl[kg][hh * 2]);
#pragma unroll
            for (int kg = 0; kg < 4; kg++)
#pragma unroll
                for (int hh = 0; hh < 2; hh++)
                    mma_f16(s[kg * 2 + hh], qfl[kt], &kfh[kg][hh * 2]);
        }

        if (kb == qb) {
            int rl0 = w * 16 + grp;
            int rl1 = rl0 + 8;
#pragma unroll
            for (int nt = 0; nt < 8; nt++) {
                int cl = nt * 8 + tig * 2;
                if (cl     > rl0) s[nt][0] = -1e30f;
                if (cl + 1 > rl0) s[nt][1] = -1e30f;
                if (cl     > rl1) s[nt][2] = -1e30f;
                if (cl + 1 > rl1) s[nt][3] = -1e30f;
            }
        }

        {
            float mx0 = -1e30f, mx1 = -1e30f;
#pragma unroll
            for (int nt = 0; nt < 8; nt++) {
                mx0 = fmaxf(mx0, fmaxf(s[nt][0], s[nt][1]));
                mx1 = fmaxf(mx1, fmaxf(s[nt][2], s[nt][3]));
            }
            mx0 = fmaxf(mx0, __shfl_xor_sync(0xffffffffu, mx0, 1));
            mx0 = fmaxf(mx0, __shfl_xor_sync(0xffffffffu, mx0, 2));
            mx1 = fmaxf(mx1, __shfl_xor_sync(0xffffffffu, mx1, 1));
            mx1 = fmaxf(mx1, __shfl_xor_sync(0xffffffffu, mx1, 2));
            float mn0 = fmaxf(m0, mx0);
            float mn1 = fmaxf(m1, mx1);
            float a0 = __expf(m0 - mn0);
            float a1 = __expf(m1 - mn1);
            float su0 = 0.f, su1 = 0.f;
#pragma unroll
            for (int nt = 0; nt < 8; nt++) {
                s[nt][0] = __expf(s[nt][0] - mn0); su0 += s[nt][0];
                s[nt][1] = __expf(s[nt][1] - mn0); su0 += s[nt][1];
                s[nt][2] = __expf(s[nt][2] - mn1); su1 += s[nt][2];
                s[nt][3] = __expf(s[nt][3] - mn1); su1 += s[nt][3];
            }
            su0 += __shfl_xor_sync(0xffffffffu, su0, 1);
            su0 += __shfl_xor_sync(0xffffffffu, su0, 2);
            su1 += __shfl_xor_sync(0xffffffffu, su1, 1);
            su1 += __shfl_xor_sync(0xffffffffu, su1, 2);
            l0 = l0 * a0 + su0;
            l1 = l1 * a1 + su1;
            m0 = mn0;
            m1 = mn1;
#pragma unroll
            for (int dn = 0; dn < 8; dn++) {
                o[dn][0] *= a0; o[dn][1] *= a0;
                o[dn][2] *= a1; o[dn][3] *= a1;
            }
        }

        // PV with fp16 P (2 terms): P*Vhi + P*Vlo
#pragma unroll
        for (int kt = 0; kt < 4; kt++) {
            uint32_t a[4];
            a[0] = packh2(s[2 * kt][0],     s[2 * kt][1]);
            a[1] = packh2(s[2 * kt][2],     s[2 * kt][3]);
            a[2] = packh2(s[2 * kt + 1][0], s[2 * kt + 1][1]);
            a[3] = packh2(s[2 * kt + 1][2], s[2 * kt + 1][3]);
            uint32_t vfh[4][4], vfl[4][4];
#pragma unroll
            for (int db = 0; db < 4; db++) {
                uint32_t addr = sb + 2 * FARR + (uint32_t)(kt * 16 * FPITCHB) + (uint32_t)(db * 32) + voffl;
                LDSM4T(vfh[db], addr);
                LDSM4T(vfl[db], addr + FARR);
            }
#pragma unroll
            for (int db = 0; db < 4; db++)
#pragma unroll
                for (int hh = 0; hh < 2; hh++)
                    mma_f16(o[db * 2 + hh], a, &vfh[db][hh * 2]);
#pragma unroll
            for (int db = 0; db < 4; db++)
#pragma unroll
                for (int hh = 0; hh < 2; hh++)
                    mma_f16(o[db * 2 + hh], a, &vfl[db][hh * 2]);
        }
    }

    {
        float i0 = 1.0f / l0;
        float i1 = 1.0f / l1;
        size_t row0 = (size_t)(b * Sc + qb * 64 + w * 16 + grp);
#pragma unroll
        for (int dn = 0; dn < 8; dn++) {
            int col = h * HDc + dn * 8 + tig * 2;
            __half2 p0 = __floats2half2_rn(o[dn][0] * i0, o[dn][1] * i0);
            __half2 p1 = __floats2half2_rn(o[dn][2] * i1, o[dn][3] * i1);
            *(__half2*)&aout[row0 * Hc + col] = p0;
            *(__half2*)&aout[(row0 + 8) * Hc + col] = p1;
        }
    }
}

// ---------------------------------------------------------------------------
// Launch
// ---------------------------------------------------------------------------
extern "C" void kernel_launch(void* const* d_in, const int* in_sizes, int n_in,
                              void* d_out, int out_size) {
    const int*   input_ids = (const int*)d_in[0];
    const int*   positions = (const int*)d_in[1];
    const float* embed     = (const float*)d_in[2];
    const float* w_qkv     = (const float*)d_in[3];
    const float* w_o       = (const float*)d_in[4];
    const float* w_gate_up = (const float*)d_in[5];
    const float* w_down    = (const float*)d_in[6];
    const float* ln1_w     = (const float*)d_in[7];
    const float* ln2_w     = (const float*)d_in[8];
    const float* norm_w    = (const float*)d_in[9];
    float* out = (float*)d_out;

    float *res;
    __half *hn, *at, *ac, *wh, *wl, *qh, *ql, *kh, *kl, *vh, *vl;
    cudaGetSymbolAddress((void**)&res,  g_res);
    cudaGetSymbolAddress((void**)&hn,   g_hn);
    cudaGetSymbolAddress((void**)&at,   g_at);
    cudaGetSymbolAddress((void**)&ac,   g_ac);
    cudaGetSymbolAddress((void**)&wh,   g_wh);
    cudaGetSymbolAddress((void**)&wl,   g_wl);
    cudaGetSymbolAddress((void**)&qh,   g_qh);
    cudaGetSymbolAddress((void**)&ql,   g_ql);
    cudaGetSymbolAddress((void**)&kh,   g_kh);
    cudaGetSymbolAddress((void**)&kl,   g_kl);
    cudaGetSymbolAddress((void**)&vh,   g_vh);
    cudaGetSymbolAddress((void**)&vl,   g_vl);

    cudaFuncSetAttribute(flash_mma, cudaFuncAttributeMaxDynamicSharedMemorySize, FLASH_SMEM);
    cudaFuncSetAttribute(gemm_f16<2>, cudaFuncAttributeMaxDynamicSharedMemorySize, GEMM_SMEM);
    cudaFuncSetAttribute(gemm_f16<1>, cudaFuncAttributeMaxDynamicSharedMemorySize, GEMM_SMEM);

    prep_weights<<<2 * TILES_PER_LAYER, dim3(32, 8)>>>(
        w_qkv, w_o, w_gate_up, w_down, wh, wl);
    rope_table_kernel<<<Sc, 32>>>(positions);

    embed_kernel<<<Tc, 256>>>(input_ids, embed, res);

    for (int l = 0; l < Lc; l++) {
        __half* whl = wh + (size_t)l * WT_PER_L;
        __half* wll = wl + (size_t)l * WT_PER_L;

        addnorm_kernel<<<Tc, 256>>>(res, ln1_w + (size_t)l * Hc, nullptr, hn);

        // QKV projection with fused RoPE (table) + split-fp16 scatter
        gemm_f16<2><<<dim3(Tc / 128, QKVN / 128), 256, GEMM_SMEM>>>(
            hn, whl + WT_QKV_OFF, wll + WT_QKV_OFF, nullptr, nullptr, nullptr,
            qh, ql, kh, kl, vh, vl, Tc, QKVN, Hc);

        flash_mma<<<dim3(Sc / 64, NHc, Bc), 128, FLASH_SMEM>>>(
            qh, ql, kh, kl, vh, vl, at);

        gemm_f16<2><<<dim3(Tc / 128, Hc / 128), 256, GEMM_SMEM>>>(
            at, whl + WT_O_OFF, wll + WT_O_OFF, res, res, nullptr,
            nullptr, nullptr, nullptr, nullptr, nullptr, nullptr,
            Tc, Hc, Hc);

        addnorm_kernel<<<Tc, 256>>>(res, ln2_w + (size_t)l * Hc, nullptr, hn);

        gemm_f16<1><<<dim3(Tc / 128, GUN / 128), 256, GEMM_SMEM>>>(
            hn, whl + WT_GU_OFF, nullptr, nullptr, nullptr, ac,
            nullptr, nullptr, nullptr, nullptr, nullptr, nullptr,
            Tc, GUN, Hc);

        gemm_f16<1><<<dim3(Tc / 128, Hc / 128), 256, GEMM_SMEM>>>(
            ac, whl + WT_DN_OFF, nullptr, res, res, nullptr,
            nullptr, nullptr, nullptr, nullptr, nullptr, nullptr,
            Tc, Hc, Ic);
    }

    addnorm_kernel<<<Tc, 256>>>(res, norm_w, out, nullptr);
}

// round 16
// speedup vs baseline: 1.0722x; 1.0523x over previous
#include <cuda_runtime.h>
#include <cuda_fp16.h>
#include <math.h>
#include <stdint.h>

// ---------------------------------------------------------------------------
// Model constants
// ---------------------------------------------------------------------------
#define Lc 2
#define Hc 2048
#define NHc 32
#define NKVc 4
#define HDc 64
#define Ic 5632
#define Bc 2
#define Sc 1024
#define Tc (Bc * Sc)                   // 2048 tokens
#define QKVN ((NHc + 2 * NKVc) * HDc)  // 2560
#define GUN (2 * Ic)                   // 11264
#define EPSc 1e-5f
#define WSCALE 64.0f
#define WINV   0.015625f               // 1/64
#define ROPE_LT 0.2878231366f          // ln(10000)/32

// ---------------------------------------------------------------------------
// Scratch (static device globals; no allocation allowed)
// ---------------------------------------------------------------------------
__device__ float g_res [Tc * Hc];

// fp16 activations (GEMM A operands)
__device__ __half g_hn [Tc * Hc];
__device__ __half g_at [Tc * Hc];
__device__ __half g_ac [(size_t)Tc * Ic];

// split fp16 Q (pre-scaled by 0.125) and KV caches
__device__ __half g_qh [Tc * Hc];
__device__ __half g_ql [Tc * Hc];
__device__ __half g_kh [Bc * NKVc * Sc * HDc];
__device__ __half g_kl [Bc * NKVc * Sc * HDc];
__device__ __half g_vh [Bc * NKVc * Sc * HDc];
__device__ __half g_vl [Bc * NKVc * Sc * HDc];

// RoPE cos/sin table [seq][32]
__device__ float2 g_rope[Sc * 32];

// Transposed split weights (x64 scaled, fp16 hi+lo exact 2-term):
// per layer [qkv_t(QKVN,H) | o_t(H,H) | gu_t(GUN,H, gate/up interleaved) | down_t(H,I)]
// lo is only populated for qkv and o (gu/dn run 1-term and never read it).
#define WT_QKV_OFF 0
#define WT_O_OFF   ((size_t)QKVN * Hc)
#define WT_GU_OFF  (WT_O_OFF + (size_t)Hc * Hc)
#define WT_DN_OFF  (WT_GU_OFF + (size_t)GUN * Hc)
#define WT_PER_L   (WT_DN_OFF + (size_t)Hc * Ic)
__device__ __half g_wh[2 * WT_PER_L];
__device__ __half g_wl[2 * WT_PER_L];

// ---------------------------------------------------------------------------
// Helpers
// ---------------------------------------------------------------------------
__device__ __forceinline__ uint32_t smem_u32(const void* p) {
    uint32_t a;
    asm("{ .reg .u64 t; cvta.to.shared.u64 t, %1; cvt.u32.u64 %0, t; }"
        : "=r"(a) : "l"(p));
    return a;
}

__device__ __forceinline__ void cp_async16(uint32_t smem_addr, const void* gptr) {
    asm volatile("cp.async.cg.shared.global [%0], [%1], 16;"
                 :: "r"(smem_addr), "l"(gptr) : "memory");
}
#define CP_COMMIT() asm volatile("cp.async.commit_group;" ::: "memory")
#define CP_WAIT0()  asm volatile("cp.async.wait_group 0;" ::: "memory")
#define CP_WAIT2()  asm volatile("cp.async.wait_group 2;" ::: "memory")

__device__ __forceinline__ void mma_f16(float* d, const uint32_t* a, const uint32_t* b) {
    asm volatile(
        "mma.sync.aligned.m16n8k16.row.col.f32.f16.f16.f32 "
        "{%0,%1,%2,%3}, {%4,%5,%6,%7}, {%8,%9}, {%0,%1,%2,%3};"
        : "+f"(d[0]), "+f"(d[1]), "+f"(d[2]), "+f"(d[3])
        : "r"(a[0]), "r"(a[1]), "r"(a[2]), "r"(a[3]),
          "r"(b[0]), "r"(b[1]));
}

#define LDSM4(R, A) \
    asm volatile("ldmatrix.sync.aligned.m8n8.x4.shared.b16 {%0,%1,%2,%3}, [%4];" \
        : "=r"((R)[0]), "=r"((R)[1]), "=r"((R)[2]), "=r"((R)[3]) : "r"(A))

#define LDSM4T(R, A) \
    asm volatile("ldmatrix.sync.aligned.m8n8.x4.trans.shared.b16 {%0,%1,%2,%3}, [%4];" \
        : "=r"((R)[0]), "=r"((R)[1]), "=r"((R)[2]), "=r"((R)[3]) : "r"(A))

__device__ __forceinline__ void split2h(float x, __half& hi, __half& lo) {
    hi = __float2half_rn(x);
    lo = __float2half_rn(x - __half2float(hi));
}

__device__ __forceinline__ uint32_t packh2(float a, float b) {
    __half2 h = __floats2half2_rn(a, b);
    return *(uint32_t*)&h;
}

// ---------------------------------------------------------------------------
// RoPE table (bit-identical expressions to the fused-epilogue math)
// ---------------------------------------------------------------------------
__global__ void rope_table_kernel(const int* __restrict__ pos) {
    int s = blockIdx.x;
    int j = threadIdx.x;
    float p = (float)pos[s];
    float ang = p * __expf(-(float)j * ROPE_LT);
    g_rope[s * 32 + j] = make_float2(cosf(ang), sinf(ang));
}

// ---------------------------------------------------------------------------
// Fused weight prep v2: transpose + x64 scale + fp16 split.
// 32(K) x 128(N) tiles, float4 reads, conflict-free transposed smem reads.
// lo written only for qkv/o (gu/dn consumers are 1-term).
// Per-layer tiles: qkv 64x20=1280 | o 64x16=1024 | gu 64x88=5632 | dn 176x16=2816
// ---------------------------------------------------------------------------
#define PREP_TPL 10752           // tiles per layer
__global__ void prep_weights(const float* __restrict__ wqkv,
                             const float* __restrict__ wo,
                             const float* __restrict__ wgu,
                             const float* __restrict__ wdn,
                             __half* __restrict__ wth,
                             __half* __restrict__ wtl) {
    __shared__ float tile[32][133];   // 5*tx mod 32 -> conflict-free transpose
    int bid = blockIdx.x;
    int l = 0;
    if (bid >= PREP_TPL) { l = 1; bid -= PREP_TPL; }
    size_t loff = (size_t)l * WT_PER_L;

    const float* src;
    __half *hi, *lo;
    int K, N;
    int gu_mode = 0;
    int need_lo;
    if (bid < 1280) {
        src = wqkv + (size_t)l * Hc * QKVN;
        hi = wth + loff + WT_QKV_OFF; lo = wtl + loff + WT_QKV_OFF;
        K = Hc; N = QKVN; need_lo = 1;
    } else if (bid < 2304) {
        bid -= 1280;
        src = wo + (size_t)l * Hc * Hc;
        hi = wth + loff + WT_O_OFF; lo = wtl + loff + WT_O_OFF;
        K = Hc; N = Hc; need_lo = 1;
    } else if (bid < 7936) {
        bid -= 2304;
        src = wgu + (size_t)l * Hc * GUN;
        hi = wth + loff + WT_GU_OFF; lo = nullptr;
        K = Hc; N = GUN; need_lo = 0;
        gu_mode = 1;
    } else {
        bid -= 7936;
        src = wdn + (size_t)l * Ic * Hc;
        hi = wth + loff + WT_DN_OFF; lo = nullptr;
        K = Ic; N = Hc; need_lo = 0;
    }
    int tilesX = N >> 7;              // N / 128
    int nb = (bid % tilesX) * 128;
    int kb = (bid / tilesX) * 32;

    int tx = threadIdx.x;             // 0..31
    int ty = threadIdx.y;             // 0..7

    // read: each warp (fixed ty) loads rows ty, ty+8, ty+16, ty+24 (float4)
#pragma unroll
    for (int i = ty; i < 32; i += 8) {
        float4 v = *(const float4*)(src + (size_t)(kb + i) * N + nb + tx * 4);
        tile[i][tx * 4 + 0] = v.x;
        tile[i][tx * 4 + 1] = v.y;
        tile[i][tx * 4 + 2] = v.z;
        tile[i][tx * 4 + 3] = v.w;
    }
    __syncthreads();

    // write: thread (tx,ty) covers cols ty*16+j (j 0..15), K index kb+tx
#pragma unroll
    for (int j = 0; j < 16; j++) {
        int c = ty * 16 + j;          // 0..127 (col within tile)
        float v = tile[tx][c] * WSCALE;
        int col = nb + c;
        if (gu_mode) col = (col < Ic) ? (2 * col) : (2 * (col - Ic) + 1);
        size_t idx = (size_t)col * K + kb + tx;
        __half h = __float2half_rn(v);
        hi[idx] = h;
        if (need_lo) lo[idx] = __float2half_rn(v - __half2float(h));
    }
}

// ---------------------------------------------------------------------------
// fp16 GEMM, templated on weight TERMS (2 = exact split, 1 = fp16 weights).
// Epilogue modes:
//   actout != nullptr : interleaved (gate,up) cols -> silu(g)*u fp16
//   qh     != nullptr : QKV mode -> RoPE (table) + split-fp16 scatter
//   else              : fp32 C (+ optional addend)
// ---------------------------------------------------------------------------
#define RPITCH 48
#define ARRB   (128 * RPITCH)
#define STAGEB (3 * ARRB)
#define GEMM_SMEM (4 * STAGEB)

template <int TERMS>
__global__ void __launch_bounds__(256, 2)
gemm_f16(const __half* __restrict__ A,
         const __half* __restrict__ Wh,
         const __half* __restrict__ Wl,
         float* __restrict__ C, const float* __restrict__ addend,
         __half* __restrict__ actout,
         __half* __restrict__ qh, __half* __restrict__ ql,
         __half* __restrict__ kh, __half* __restrict__ kl,
         __half* __restrict__ vh, __half* __restrict__ vl,
         int M, int N, int K) {
    extern __shared__ char smraw[];
    uint32_t sbase = smem_u32(smraw);

    const int tid  = threadIdx.x;
    const int warp = tid >> 5;
    const int lane = tid & 31;
    const int wm   = (warp >> 1) * 32;
    const int wn   = (warp & 1) * 64;
    const int grp  = lane >> 2;
    const int tig  = lane & 3;

    const int m0 = blockIdx.x * 128;
    const int n0 = blockIdx.y * 128;

    const int li = lane >> 3;
    const int lr = lane & 7;
    const uint32_t aoffl = (uint32_t)(((li & 1) * 8 + lr) * RPITCH + (li >> 1) * 16);
    const uint32_t boffl = (uint32_t)(((li >> 1) * 8 + lr) * RPITCH + (li & 1) * 16);

    const int r0   = tid >> 1;
    const int half = tid & 1;
    const uint32_t sdst = (uint32_t)(r0 * RPITCH + half * 16);
    const __half* pA  = A  + (size_t)(m0 + r0) * K + half * 8;
    const __half* pWh = Wh + (size_t)(n0 + r0) * K + half * 8;
    const __half* pWl = (TERMS == 2) ? (Wl + (size_t)(n0 + r0) * K + half * 8) : nullptr;

    const int nkt = K >> 4;

    float c[2][8][4];
#pragma unroll
    for (int mt = 0; mt < 2; mt++)
#pragma unroll
        for (int nt = 0; nt < 8; nt++)
#pragma unroll
            for (int i = 0; i < 4; i++) c[mt][nt][i] = 0.f;

#pragma unroll
    for (int s = 0; s < 3; s++) {
        uint32_t b = sbase + (uint32_t)s * STAGEB + sdst;
        int ko = s * 16;
        cp_async16(b,            pA  + ko);
        cp_async16(b + ARRB,     pWh + ko);
        if (TERMS == 2) cp_async16(b + 2 * ARRB, pWl + ko);
        CP_COMMIT();
    }

    for (int kt = 0; kt < nkt; kt++) {
        CP_WAIT2();
        __syncthreads();

        uint32_t sb = sbase + (uint32_t)(kt & 3) * STAGEB;

        uint32_t a[2][4];
#pragma unroll
        for (int mt = 0; mt < 2; mt++) {
            uint32_t aaddr = sb + (uint32_t)((wm + mt * 16) * RPITCH) + aoffl;
            LDSM4(a[mt], aaddr);
        }
#pragma unroll
        for (int nh = 0; nh < 2; nh++) {
            uint32_t wh[2][4], wl[2][4];
#pragma unroll
            for (int pq = 0; pq < 2; pq++) {
                uint32_t baddr = sb + ARRB +
                                 (uint32_t)((wn + nh * 32 + pq * 16) * RPITCH) + boffl;
                LDSM4(wh[pq], baddr);
                if (TERMS == 2) LDSM4(wl[pq], baddr + ARRB);
            }
#pragma unroll
            for (int mt = 0; mt < 2; mt++)
#pragma unroll
                for (int pq = 0; pq < 2; pq++)
#pragma unroll
                    for (int h = 0; h < 2; h++)
                        mma_f16(c[mt][nh * 4 + pq * 2 + h], a[mt], &wh[pq][h * 2]);
            if (TERMS == 2) {
#pragma unroll
                for (int mt = 0; mt < 2; mt++)
#pragma unroll
                    for (int pq = 0; pq < 2; pq++)
#pragma unroll
                        for (int h = 0; h < 2; h++)
                            mma_f16(c[mt][nh * 4 + pq * 2 + h], a[mt], &wl[pq][h * 2]);
            }
        }

        if (kt + 3 < nkt) {
            uint32_t b = sbase + (uint32_t)((kt + 3) & 3) * STAGEB + sdst;
            int ko = (kt + 3) * 16;
            cp_async16(b,            pA  + ko);
            cp_async16(b + ARRB,     pWh + ko);
            if (TERMS == 2) cp_async16(b + 2 * ARRB, pWl + ko);
        }
        CP_COMMIT();
    }

    if (actout) {
#pragma unroll
        for (int mt = 0; mt < 2; mt++) {
            int row = m0 + wm + mt * 16 + grp;
#pragma unroll
            for (int nt = 0; nt < 8; nt++) {
                int col = n0 + wn + nt * 8 + tig * 2;
                int pair = col >> 1;
                {
                    float g = c[mt][nt][0] * WINV;
                    float u = c[mt][nt][1] * WINV;
                    float sig = 1.0f / (1.0f + __expf(-g));
                    actout[(size_t)row * Ic + pair] = __float2half_rn(g * sig * u);
                }
                {
                    float g = c[mt][nt][2] * WINV;
                    float u = c[mt][nt][3] * WINV;
                    float sig = 1.0f / (1.0f + __expf(-g));
                    actout[(size_t)(row + 8) * Ic + pair] = __float2half_rn(g * sig * u);
                }
            }
        }
    } else if (qh) {
        // QKV mode: RoPE via table + split-fp16 scatter.
        int head64 = n0 + wn;
#pragma unroll
        for (int mt = 0; mt < 2; mt++) {
#pragma unroll
            for (int r = 0; r < 2; r++) {
                int tok = m0 + wm + mt * 16 + grp + r * 8;
                int bb = tok / Sc;
                int ss = tok - bb * Sc;
                const float2* rt = g_rope + ss * 32;
                if (head64 < NHc * HDc) {
                    int head = head64 >> 6;
                    size_t base = (size_t)tok * Hc + head * HDc;
#pragma unroll
                    for (int nt = 0; nt < 4; nt++) {
#pragma unroll
                        for (int e = 0; e < 2; e++) {
                            int j = nt * 8 + tig * 2 + e;
                            float x1 = c[mt][nt][r * 2 + e] * WINV;
                            float x2 = c[mt][nt + 4][r * 2 + e] * WINV;
                            float2 cs = rt[j];
                            float r1 = (x1 * cs.x - x2 * cs.y) * 0.125f;
                            float r2 = (x2 * cs.x + x1 * cs.y) * 0.125f;
                            __half h1, l1, h2, l2;
                            split2h(r1, h1, l1);
                            split2h(r2, h2, l2);
                            qh[base + j] = h1;       ql[base + j] = l1;
                            qh[base + j + 32] = h2;  ql[base + j + 32] = l2;
                        }
                    }
                } else if (head64 < (NHc + NKVc) * HDc) {
                    int hk = (head64 - NHc * HDc) >> 6;
                    size_t base = (((size_t)(bb * NKVc + hk)) * Sc + ss) * HDc;
#pragma unroll
                    for (int nt = 0; nt < 4; nt++) {
#pragma unroll
                        for (int e = 0; e < 2; e++) {
                            int j = nt * 8 + tig * 2 + e;
                            float x1 = c[mt][nt][r * 2 + e] * WINV;
                            float x2 = c[mt][nt + 4][r * 2 + e] * WINV;
                            float2 cs = rt[j];
                            float r1 = x1 * cs.x - x2 * cs.y;
                            float r2 = x2 * cs.x + x1 * cs.y;
                            __half h1, l1, h2, l2;
                            split2h(r1, h1, l1);
                            split2h(r2, h2, l2);
                            kh[base + j] = h1;       kl[base + j] = l1;
                            kh[base + j + 32] = h2;  kl[base + j + 32] = l2;
                        }
                    }
                } else {
                    int hv = (head64 - (NHc + NKVc) * HDc) >> 6;
                    size_t base = (((size_t)(bb * NKVc + hv)) * Sc + ss) * HDc;
#pragma unroll
                    for (int nt = 0; nt < 8; nt++) {
#pragma unroll
                        for (int e = 0; e < 2; e++) {
                            int d = nt * 8 + tig * 2 + e;
                            float v = c[mt][nt][r * 2 + e] * WINV;
                            __half h1, l1;
                            split2h(v, h1, l1);
                            vh[base + d] = h1;  vl[base + d] = l1;
                        }
                    }
                }
            }
        }
    } else {
#pragma unroll
        for (int mt = 0; mt < 2; mt++) {
            int row = m0 + wm + mt * 16 + grp;
#pragma unroll
            for (int nt = 0; nt < 8; nt++) {
                int col = n0 + wn + nt * 8 + tig * 2;
                size_t i0 = (size_t)row * N + col;
                size_t i1 = (size_t)(row + 8) * N + col;
                float2 v0 = make_float2(c[mt][nt][0] * WINV, c[mt][nt][1] * WINV);
                float2 v1 = make_float2(c[mt][nt][2] * WINV, c[mt][nt][3] * WINV);
                if (addend) {
                    float2 a0 = *(const float2*)(addend + i0);
                    float2 a1 = *(const float2*)(addend + i1);
                    v0.x += a0.x; v0.y += a0.y;
                    v1.x += a1.x; v1.y += a1.y;
                }
                *(float2*)(C + i0) = v0;
                *(float2*)(C + i1) = v1;
            }
        }
    }
}

// ---------------------------------------------------------------------------
// Embedding gather
// ---------------------------------------------------------------------------
__global__ void embed_kernel(const int* __restrict__ ids,
                             const float* __restrict__ embed,
                             float* __restrict__ res) {
    int t = blockIdx.x;
    int id = ids[t];
    const float4* src = (const float4*)(embed + (size_t)id * Hc);
    float4* dst = (float4*)(res + (size_t)t * Hc);
    for (int i = threadIdx.x; i < Hc / 4; i += blockDim.x)
        dst[i] = src[i];
}

// ---------------------------------------------------------------------------
// RMSNorm. Output fp32 and/or fp16.
// ---------------------------------------------------------------------------
__global__ void addnorm_kernel(const float* __restrict__ res,
                               const float* __restrict__ w,
                               float* __restrict__ outf,
                               __half* __restrict__ oh) {
    int t = blockIdx.x;
    int tid = threadIdx.x;
    const float* rp = res + (size_t)t * Hc;
    float vals[8];
    float ss = 0.f;
#pragma unroll
    for (int i = 0; i < 8; i++) {
        int idx = tid + i * 256;
        float v = rp[idx];
        vals[i] = v;
        ss += v * v;
    }
    __shared__ float warp_s[8];
#pragma unroll
    for (int off = 16; off > 0; off >>= 1)
        ss += __shfl_down_sync(0xffffffff, ss, off);
    if ((tid & 31) == 0) warp_s[tid >> 5] = ss;
    __syncthreads();
    if (tid < 8) {
        float v = warp_s[tid];
#pragma unroll
        for (int off = 4; off > 0; off >>= 1)
            v += __shfl_down_sync(0xff, v, off);
        if (tid == 0) warp_s[0] = v;
    }
    __syncthreads();
    float inv = rsqrtf(warp_s[0] * (1.0f / Hc) + EPSc);
#pragma unroll
    for (int i = 0; i < 8; i++) {
        int idx = tid + i * 256;
        float o = vals[i] * inv * w[idx];
        if (outf) outf[(size_t)t * Hc + idx] = o;
        if (oh)   oh[(size_t)t * Hc + idx] = __float2half_rn(o);
    }
}

// ---------------------------------------------------------------------------
// Flash attention on fp16 MMA. One block = 64 queries of one (b, head),
// 4 warps x 16 rows, 128 threads. QK: 3-term split (exact).
// PV: P fp16 x V 2-term split (2 terms). Heavy blocks first.
// ---------------------------------------------------------------------------
#define FPITCHB 144
#define FARR    (64 * FPITCHB)
#define FBUF    (4 * FARR)
#define FLASH_SMEM (2 * FBUF)

__global__ void __launch_bounds__(128)
flash_mma(const __half* __restrict__ qhg, const __half* __restrict__ qlg,
          const __half* __restrict__ khg, const __half* __restrict__ klg,
          const __half* __restrict__ vhg, const __half* __restrict__ vlg,
          __half* __restrict__ aout) {
    extern __shared__ char smraw[];
    uint32_t sbase = smem_u32(smraw);

    const int qb = (int)gridDim.x - 1 - (int)blockIdx.x;   // heavy-first
    const int h  = blockIdx.y;
    const int b  = blockIdx.z;
    const int hkv = h / (NHc / NKVc);
    const int tid = threadIdx.x;
    const int w   = tid >> 5;
    const int lane = tid & 31;
    const int grp = lane >> 2;
    const int tig = lane & 3;
    const int li = lane >> 3;
    const int lr = lane & 7;
    const uint32_t boffl = (uint32_t)(((li >> 1) * 8 + lr) * FPITCHB + (li & 1) * 16);
    const uint32_t voffl = (uint32_t)(((li & 1) * 8 + lr) * FPITCHB + (li >> 1) * 16);

    uint32_t qfh[4][4], qfl[4][4];
    {
        int row0 = b * Sc + qb * 64 + w * 16 + grp;
#pragma unroll
        for (int kt = 0; kt < 4; kt++) {
#pragma unroll
            for (int i = 0; i < 4; i++) {
                int row = row0 + (i & 1) * 8;
                int col = h * HDc + kt * 16 + (i >> 1) * 8 + tig * 2;
                qfh[kt][i] = *(const uint32_t*)&qhg[(size_t)row * Hc + col];
                qfl[kt][i] = *(const uint32_t*)&qlg[(size_t)row * Hc + col];
            }
        }
    }

    float o[8][4];
#pragma unroll
    for (int dn = 0; dn < 8; dn++)
#pragma unroll
        for (int i = 0; i < 4; i++) o[dn][i] = 0.f;
    float m0 = -1e30f, m1 = -1e30f, l0 = 0.f, l1 = 0.f;

    const size_t kvbase = ((size_t)(b * NKVc + hkv)) * Sc;

    {
        uint32_t bb = sbase;
#pragma unroll
        for (int i = 0; i < 4; i++) {
            int chunk = tid + i * 128;
            int r = chunk >> 3, cc = chunk & 7;
            uint32_t so = (uint32_t)(r * FPITCHB + cc * 16);
            size_t go = (kvbase + r) * HDc + cc * 8;
            cp_async16(bb + so,            khg + go);
            cp_async16(bb + FARR + so,     klg + go);
            cp_async16(bb + 2 * FARR + so, vhg + go);
            cp_async16(bb + 3 * FARR + so, vlg + go);
        }
        CP_COMMIT();
    }

    for (int kb = 0; kb <= qb; kb++) {
        CP_WAIT0();
        __syncthreads();

        if (kb + 1 <= qb) {
            uint32_t bb = sbase + (uint32_t)((kb + 1) & 1) * FBUF;
#pragma unroll
            for (int i = 0; i < 4; i++) {
                int chunk = tid + i * 128;
                int r = chunk >> 3, cc = chunk & 7;
                uint32_t so = (uint32_t)(r * FPITCHB + cc * 16);
                size_t go = (kvbase + (kb + 1) * 64 + r) * HDc + cc * 8;
                cp_async16(bb + so,            khg + go);
                cp_async16(bb + FARR + so,     klg + go);
                cp_async16(bb + 2 * FARR + so, vhg + go);
                cp_async16(bb + 3 * FARR + so, vlg + go);
            }
            CP_COMMIT();
        }

        uint32_t sb = sbase + (uint32_t)(kb & 1) * FBUF;

        float s[8][4];
#pragma unroll
        for (int nt = 0; nt < 8; nt++)
#pragma unroll
            for (int i = 0; i < 4; i++) s[nt][i] = 0.f;

#pragma unroll
        for (int kt = 0; kt < 4; kt++) {
            uint32_t kfh[4][4], kfl[4][4];
#pragma unroll
            for (int kg = 0; kg < 4; kg++) {
                uint32_t addr = sb + (uint32_t)(kg * 16 * FPITCHB) + (uint32_t)(kt * 32) + boffl;
                LDSM4(kfh[kg], addr);
                LDSM4(kfl[kg], addr + FARR);
            }
#pragma unroll
            for (int kg = 0; kg < 4; kg++)
#pragma unroll
                for (int hh = 0; hh < 2; hh++)
                    mma_f16(s[kg * 2 + hh], qfh[kt], &kfh[kg][hh * 2]);
#pragma unroll
            for (int kg = 0; kg < 4; kg++)
#pragma unroll
                for (int hh = 0; hh < 2; hh++)
                    mma_f16(s[kg * 2 + hh], qfh[kt], &kfl[kg][hh * 2]);
#pragma unroll
            for (int kg = 0; kg < 4; kg++)
#pragma unroll
                for (int hh = 0; hh < 2; hh++)
                    mma_f16(s[kg * 2 + hh], qfl[kt], &kfh[kg][hh * 2]);
        }

        if (kb == qb) {
            int rl0 = w * 16 + grp;
            int rl1 = rl0 + 8;
#pragma unroll
            for (int nt = 0; nt < 8; nt++) {
                int cl = nt * 8 + tig * 2;
                if (cl     > rl0) s[nt][0] = -1e30f;
                if (cl + 1 > rl0) s[nt][1] = -1e30f;
                if (cl     > rl1) s[nt][2] = -1e30f;
                if (cl + 1 > rl1) s[nt][3] = -1e30f;
            }
        }

        {
            float mx0 = -1e30f, mx1 = -1e30f;
#pragma unroll
            for (int nt = 0; nt < 8; nt++) {
                mx0 = fmaxf(mx0, fmaxf(s[nt][0], s[nt][1]));
                mx1 = fmaxf(mx1, fmaxf(s[nt][2], s[nt][3]));
            }
            mx0 = fmaxf(mx0, __shfl_xor_sync(0xffffffffu, mx0, 1));
            mx0 = fmaxf(mx0, __shfl_xor_sync(0xffffffffu, mx0, 2));
            mx1 = fmaxf(mx1, __shfl_xor_sync(0xffffffffu, mx1, 1));
            mx1 = fmaxf(mx1, __shfl_xor_sync(0xffffffffu, mx1, 2));
            float mn0 = fmaxf(m0, mx0);
            float mn1 = fmaxf(m1, mx1);
            float a0 = __expf(m0 - mn0);
            float a1 = __expf(m1 - mn1);
            float su0 = 0.f, su1 = 0.f;
#pragma unroll
            for (int nt = 0; nt < 8; nt++) {
                s[nt][0] = __expf(s[nt][0] - mn0); su0 += s[nt][0];
                s[nt][1] = __expf(s[nt][1] - mn0); su0 += s[nt][1];
                s[nt][2] = __expf(s[nt][2] - mn1); su1 += s[nt][2];
                s[nt][3] = __expf(s[nt][3] - mn1); su1 += s[nt][3];
            }
            su0 += __shfl_xor_sync(0xffffffffu, su0, 1);
            su0 += __shfl_xor_sync(0xffffffffu, su0, 2);
            su1 += __shfl_xor_sync(0xffffffffu, su1, 1);
            su1 += __shfl_xor_sync(0xffffffffu, su1, 2);
            l0 = l0 * a0 + su0;
            l1 = l1 * a1 + su1;
            m0 = mn0;
            m1 = mn1;
#pragma unroll
            for (int dn = 0; dn < 8; dn++) {
                o[dn][0] *= a0; o[dn][1] *= a0;
                o[dn][2] *= a1; o[dn][3] *= a1;
            }
        }

        // PV with fp16 P (2 terms): P*Vhi + P*Vlo
#pragma unroll
        for (int kt = 0; kt < 4; kt++) {
            uint32_t a[4];
            a[0] = packh2(s[2 * kt][0],     s[2 * kt][1]);
            a[1] = packh2(s[2 * kt][2],     s[2 * kt][3]);
            a[2] = packh2(s[2 * kt + 1][0], s[2 * kt + 1][1]);
            a[3] = packh2(s[2 * kt + 1][2], s[2 * kt + 1][3]);
            uint32_t vfh[4][4], vfl[4][4];
#pragma unroll
            for (int db = 0; db < 4; db++) {
                uint32_t addr = sb + 2 * FARR + (uint32_t)(kt * 16 * FPITCHB) + (uint32_t)(db * 32) + voffl;
                LDSM4T(vfh[db], addr);
                LDSM4T(vfl[db], addr + FARR);
            }
#pragma unroll
            for (int db = 0; db < 4; db++)
#pragma unroll
                for (int hh = 0; hh < 2; hh++)
                    mma_f16(o[db * 2 + hh], a, &vfh[db][hh * 2]);
#pragma unroll
            for (int db = 0; db < 4; db++)
#pragma unroll
                for (int hh = 0; hh < 2; hh++)
                    mma_f16(o[db * 2 + hh], a, &vfl[db][hh * 2]);
        }
    }

    {
        float i0 = 1.0f / l0;
        float i1 = 1.0f / l1;
        size_t row0 = (size_t)(b * Sc + qb * 64 + w * 16 + grp);
#pragma unroll
        for (int dn = 0; dn < 8; dn++) {
            int col = h * HDc + dn * 8 + tig * 2;
            __half2 p0 = __floats2half2_rn(o[dn][0] * i0, o[dn][1] * i0);
            __half2 p1 = __floats2half2_rn(o[dn][2] * i1, o[dn][3] * i1);
            *(__half2*)&aout[row0 * Hc + col] = p0;
            *(__half2*)&aout[(row0 + 8) * Hc + col] = p1;
        }
    }
}

// ---------------------------------------------------------------------------
// Launch
// ---------------------------------------------------------------------------
extern "C" void kernel_launch(void* const* d_in, const int* in_sizes, int n_in,
                              void* d_out, int out_size) {
    const int*   input_ids = (const int*)d_in[0];
    const int*   positions = (const int*)d_in[1];
    const float* embed     = (const float*)d_in[2];
    const float* w_qkv     = (const float*)d_in[3];
    const float* w_o       = (const float*)d_in[4];
    const float* w_gate_up = (const float*)d_in[5];
    const float* w_down    = (const float*)d_in[6];
    const float* ln1_w     = (const float*)d_in[7];
    const float* ln2_w     = (const float*)d_in[8];
    const float* norm_w    = (const float*)d_in[9];
    float* out = (float*)d_out;

    float *res;
    __half *hn, *at, *ac, *wh, *wl, *qh, *ql, *kh, *kl, *vh, *vl;
    cudaGetSymbolAddress((void**)&res,  g_res);
    cudaGetSymbolAddress((void**)&hn,   g_hn);
    cudaGetSymbolAddress((void**)&at,   g_at);
    cudaGetSymbolAddress((void**)&ac,   g_ac);
    cudaGetSymbolAddress((void**)&wh,   g_wh);
    cudaGetSymbolAddress((void**)&wl,   g_wl);
    cudaGetSymbolAddress((void**)&qh,   g_qh);
    cudaGetSymbolAddress((void**)&ql,   g_ql);
    cudaGetSymbolAddress((void**)&kh,   g_kh);
    cudaGetSymbolAddress((void**)&kl,   g_kl);
    cudaGetSymbolAddress((void**)&vh,   g_vh);
    cudaGetSymbolAddress((void**)&vl,   g_vl);

    cudaFuncSetAttribute(flash_mma, cudaFuncAttributeMaxDynamicSharedMemorySize, FLASH_SMEM);
    cudaFuncSetAttribute(gemm_f16<2>, cudaFuncAttributeMaxDynamicSharedMemorySize, GEMM_SMEM);
    cudaFuncSetAttribute(gemm_f16<1>, cudaFuncAttributeMaxDynamicSharedMemorySize, GEMM_SMEM);

    prep_weights<<<2 * PREP_TPL, dim3(32, 8)>>>(
        w_qkv, w_o, w_gate_up, w_down, wh, wl);
    rope_table_kernel<<<Sc, 32>>>(positions);

    embed_kernel<<<Tc, 256>>>(input_ids, embed, res);

    for (int l = 0; l < Lc; l++) {
        __half* whl = wh + (size_t)l * WT_PER_L;
        __half* wll = wl + (size_t)l * WT_PER_L;

        addnorm_kernel<<<Tc, 256>>>(res, ln1_w + (size_t)l * Hc, nullptr, hn);

        // QKV projection with fused RoPE (table) + split-fp16 scatter
        gemm_f16<2><<<dim3(Tc / 128, QKVN / 128), 256, GEMM_SMEM>>>(
            hn, whl + WT_QKV_OFF, wll + WT_QKV_OFF, nullptr, nullptr, nullptr,
            qh, ql, kh, kl, vh, vl, Tc, QKVN, Hc);

        flash_mma<<<dim3(Sc / 64, NHc, Bc), 128, FLASH_SMEM>>>(
            qh, ql, kh, kl, vh, vl, at);

        gemm_f16<2><<<dim3(Tc / 128, Hc / 128), 256, GEMM_SMEM>>>(
            at, whl + WT_O_OFF, wll + WT_O_OFF, res, res, nullptr,
            nullptr, nullptr, nullptr, nullptr, nullptr, nullptr,
            Tc, Hc, Hc);

        addnorm_kernel<<<Tc, 256>>>(res, ln2_w + (size_t)l * Hc, nullptr, hn);

        gemm_f16<1><<<dim3(Tc / 128, GUN / 128), 256, GEMM_SMEM>>>(
            hn, whl + WT_GU_OFF, nullptr, nullptr, nullptr, ac,
            nullptr, nullptr, nullptr, nullptr, nullptr, nullptr,
            Tc, GUN, Hc);

        gemm_f16<1><<<dim3(Tc / 128, Hc / 128), 256, GEMM_SMEM>>>(
            ac, whl + WT_DN_OFF, nullptr, res, res, nullptr,
            nullptr, nullptr, nullptr, nullptr, nullptr, nullptr,
            Tc, Hc, Ic);
    }

    addnorm_kernel<<<Tc, 256>>>(res, norm_w, out, nullptr);
}